// round 5
// baseline (speedup 1.0000x reference)
#include <cuda_runtime.h>
#include <math.h>
#include <stdint.h>

#define B_ 128
#define L_ 128
#define T_ (B_*L_)
#define DIN_ 6
#define D_ 256
#define H_ 8
#define DK_ 32
#define NL_ 6
#define NE_ 8
#define DFF_ 1024
#define NOUT_ 5

#define ATTN_SMEM ((128*33 + 128*129 + 128)*4)

// ---------------- device scratch (no allocations allowed) ----------------
__device__ float g_h[T_*D_];
__device__ float g_q[T_*D_];
__device__ float g_k[T_*D_];
__device__ float g_v[T_*D_];
__device__ float g_ao[T_*D_];
__device__ float g_eo[(size_t)NE_*T_*D_];     // per-expert FFN outputs by list position
__device__ float g_hb[(size_t)NE_*T_*DFF_];   // FFN hidden (gelu output), per (e, pos)
__device__ int   g_cnt[NE_];
__device__ int   g_list[NE_*T_];
__device__ int   g_ebuf[T_*2];
__device__ int   g_pbuf[T_*2];
__device__ float g_wbuf[T_*2];

// ---------------- embed: h = x @ emb_w + emb_b ----------------
__global__ void embed_kernel(const float* __restrict__ x,
                             const float* __restrict__ w,
                             const float* __restrict__ b) {
    int t = blockIdx.x, d = threadIdx.x;
    float acc = b[d];
#pragma unroll
    for (int i = 0; i < DIN_; i++) acc += x[t*DIN_ + i] * w[i*D_ + d];
    g_h[(size_t)t*D_ + d] = acc;
}

// ---------------- TF32 tensor-core GEMM ----------------
// C[M,N] = A[M,K] @ W[K,N]  (both row-major), fused epilogues.
// Block tile 128x128, 8 warps (4M x 2N), warp tile 32x64 (2 m16 x 8 n8), K-chunk 32.
#define EPI_NONE      0
#define EPI_RES       1
#define EPI_BIAS_GELU 2
#define EPI_BIAS      3

__device__ __forceinline__ uint32_t f2tf(float x) {
    uint32_t u;
    asm("cvt.rna.tf32.f32 %0, %1;" : "=r"(u) : "f"(x));
    return u;
}

#define LDA_S 36
#define LDB_S 136

template<int EPI>
__global__ __launch_bounds__(256)
void mma_gemm(const float* __restrict__ A, int lda, size_t strideA,
              const float* __restrict__ W, int ldw, size_t strideW,
              float* __restrict__ C, int ldc, size_t strideC,
              const float* __restrict__ bias, size_t strideBias,
              const float* __restrict__ res,
              const int* __restrict__ gather, size_t strideGather,
              const int* __restrict__ cntPtr,
              int M, int N, int K) {
    __shared__ float As[128*LDA_S];
    __shared__ float Bs[32*LDB_S];

    int e = blockIdx.z;
    const float* Ae = A + (size_t)e*strideA;
    const float* We = W + (size_t)e*strideW;
    float*       Ce = C + (size_t)e*strideC;
    const float* be = bias ? bias + (size_t)e*strideBias : nullptr;
    const int*   ge = gather ? gather + (size_t)e*strideGather : nullptr;
    int Mloc = cntPtr ? cntPtr[e] : M;

    int bm = blockIdx.x * 128;
    if (bm >= Mloc) return;
    int bn = blockIdx.y * 128;

    int tid = threadIdx.x;
    int lane = tid & 31;
    int wid = tid >> 5;
    int wm = wid & 3;        // 0..3  M direction
    int wn = wid >> 2;       // 0..1  N direction

    float acc[2][8][4];
#pragma unroll
    for (int mt = 0; mt < 2; mt++)
#pragma unroll
        for (int nt = 0; nt < 8; nt++)
#pragma unroll
            for (int i = 0; i < 4; i++) acc[mt][nt][i] = 0.f;

    for (int k0 = 0; k0 < K; k0 += 32) {
        // ---- load A tile 128x32 (gathered, guarded) ----
#pragma unroll
        for (int p = 0; p < 4; p++) {
            int f = tid + p*256;
            int r = f >> 3;              // 0..127
            int c4 = (f & 7) << 2;       // 0,4,...,28
            float4 v = make_float4(0.f, 0.f, 0.f, 0.f);
            int grow = bm + r;
            if (grow < Mloc) {
                int arow = ge ? ge[grow] : grow;
                v = *(const float4*)(Ae + (size_t)arow*lda + k0 + c4);
            }
            float* dst = As + r*LDA_S + c4;
            dst[0] = __uint_as_float(f2tf(v.x));
            dst[1] = __uint_as_float(f2tf(v.y));
            dst[2] = __uint_as_float(f2tf(v.z));
            dst[3] = __uint_as_float(f2tf(v.w));
        }
        // ---- load B tile 32x128 ----
#pragma unroll
        for (int p = 0; p < 4; p++) {
            int f = tid + p*256;
            int kr = f >> 5;             // 0..31
            int c4 = (f & 31) << 2;      // 0..124
            float4 v = *(const float4*)(We + (size_t)(k0 + kr)*ldw + bn + c4);
            float* dst = Bs + kr*LDB_S + c4;
            dst[0] = __uint_as_float(f2tf(v.x));
            dst[1] = __uint_as_float(f2tf(v.y));
            dst[2] = __uint_as_float(f2tf(v.z));
            dst[3] = __uint_as_float(f2tf(v.w));
        }
        __syncthreads();

        const float* ar0 = As + (wm*32 + (lane >> 2))*LDA_S + (lane & 3);
        const float* br0 = Bs + (lane & 3)*LDB_S + wn*64 + (lane >> 2);
#pragma unroll
        for (int kk = 0; kk < 32; kk += 8) {
            uint32_t af[2][4];
#pragma unroll
            for (int mt = 0; mt < 2; mt++) {
                const float* ar = ar0 + mt*16*LDA_S + kk;
                af[mt][0] = __float_as_uint(ar[0]);
                af[mt][1] = __float_as_uint(ar[8*LDA_S]);
                af[mt][2] = __float_as_uint(ar[4]);
                af[mt][3] = __float_as_uint(ar[8*LDA_S + 4]);
            }
            uint32_t bf[8][2];
#pragma unroll
            for (int nt = 0; nt < 8; nt++) {
                const float* br = br0 + kk*LDB_S + nt*8;
                bf[nt][0] = __float_as_uint(br[0]);
                bf[nt][1] = __float_as_uint(br[4*LDB_S]);
            }
#pragma unroll
            for (int mt = 0; mt < 2; mt++)
#pragma unroll
                for (int nt = 0; nt < 8; nt++) {
                    asm volatile(
                        "mma.sync.aligned.m16n8k8.row.col.f32.tf32.tf32.f32 "
                        "{%0,%1,%2,%3}, {%4,%5,%6,%7}, {%8,%9}, {%0,%1,%2,%3};"
                        : "+f"(acc[mt][nt][0]), "+f"(acc[mt][nt][1]),
                          "+f"(acc[mt][nt][2]), "+f"(acc[mt][nt][3])
                        : "r"(af[mt][0]), "r"(af[mt][1]), "r"(af[mt][2]), "r"(af[mt][3]),
                          "r"(bf[nt][0]), "r"(bf[nt][1]));
                }
        }
        __syncthreads();
    }

    // ---- epilogue ----
#pragma unroll
    for (int mt = 0; mt < 2; mt++) {
#pragma unroll
        for (int nt = 0; nt < 8; nt++) {
            int r0 = bm + wm*32 + mt*16 + (lane >> 2);
            int c0 = bn + wn*64 + nt*8 + ((lane & 3) << 1);
#pragma unroll
            for (int i = 0; i < 4; i++) {
                int row = r0 + ((i >> 1) << 3);
                int col = c0 + (i & 1);
                if (row < Mloc) {
                    float v = acc[mt][nt][i];
                    if (EPI == EPI_BIAS_GELU) {
                        v += be[col];
                        v = 0.5f*v*(1.f + erff(v*0.7071067811865475f));
                    } else if (EPI == EPI_BIAS) {
                        v += be[col];
                    } else if (EPI == EPI_RES) {
                        v += res[(size_t)row*ldc + col];
                    }
                    Ce[(size_t)row*ldc + col] = v;
                }
            }
        }
    }
}

// ---------------- wave attention: one block per (b, head) ----------------
__global__ void attn_kernel(const float* __restrict__ q, const float* __restrict__ k,
                            const float* __restrict__ v, const float* __restrict__ wfreq,
                            const float* __restrict__ wphase, float* __restrict__ out,
                            int layer) {
    extern __shared__ float sm[];
    float* kv  = sm;                         // 128*33 (K tile, later reused as V tile)
    float* ps  = sm + 128*33;                // 128*129 score rows (padded)
    float* wav = sm + 128*33 + 128*129;      // 128 wave values

    int b = blockIdx.x >> 3, hh = blockIdx.x & 7;
    int t = threadIdx.x;
    float freq  = wfreq[layer*H_ + hh];
    float phase = wphase[layer*H_ + hh];
    wav[t] = cosf(6.283185307179586f * freq * (float)t + phase);

    const float* qb = q + (size_t)(b*L_)*D_ + hh*DK_;
    const float* kb = k + (size_t)(b*L_)*D_ + hh*DK_;
    const float* vb = v + (size_t)(b*L_)*D_ + hh*DK_;

    for (int i = t; i < L_*DK_; i += L_) {
        int r = i >> 5, c = i & 31;
        kv[r*33 + c] = kb[(size_t)r*D_ + c];
    }
    float qr[DK_];
#pragma unroll
    for (int d = 0; d < DK_; d++) qr[d] = qb[(size_t)t*D_ + d];
    __syncthreads();

    const float scale = 0.17677669529663688f;   // 32^-0.5
    float mx = -1e30f;
    for (int j = 0; j < L_; j++) {
        float s = 0.f;
#pragma unroll
        for (int d = 0; d < DK_; d++) s += qr[d]*kv[j*33 + d];
        s = s * scale * wav[j];
        ps[t*129 + j] = s;
        mx = fmaxf(mx, s);
    }
    float sum = 0.f;
    for (int j = 0; j < L_; j++) {
        float e = expf(ps[t*129 + j] - mx);
        ps[t*129 + j] = e;
        sum += e;
    }
    float inv = 1.f / sum;
    __syncthreads();   // everyone done with K tile
    for (int i = t; i < L_*DK_; i += L_) {
        int r = i >> 5, c = i & 31;
        kv[r*33 + c] = vb[(size_t)r*D_ + c];
    }
    __syncthreads();

    float o[DK_];
#pragma unroll
    for (int d = 0; d < DK_; d++) o[d] = 0.f;
    for (int j = 0; j < L_; j++) {
        float p = ps[t*129 + j];
#pragma unroll
        for (int d = 0; d < DK_; d++) o[d] += p*kv[j*33 + d];
    }
    float* ob = out + (size_t)(b*L_ + t)*D_ + hh*DK_;
#pragma unroll
    for (int d = 0; d < DK_; d++) ob[d] = o[d]*inv;
}

// ---------------- MoE router + bucketing (one warp per token) ----------------
__global__ void reset_kernel() {
    if (threadIdx.x < NE_) g_cnt[threadIdx.x] = 0;
}

__global__ void router_kernel(const float* __restrict__ rtw, const float* __restrict__ rtb) {
    int lane = threadIdx.x & 31;
    int t = blockIdx.x*8 + (threadIdx.x >> 5);
    const float* xr = g_h + (size_t)t*D_;
    float acc[NE_];
#pragma unroll
    for (int e = 0; e < NE_; e++) acc[e] = 0.f;
    for (int d = lane; d < D_; d += 32) {
        float xv = xr[d];
#pragma unroll
        for (int e = 0; e < NE_; e++) acc[e] += xv * rtw[d*NE_ + e];
    }
#pragma unroll
    for (int off = 16; off > 0; off >>= 1)
#pragma unroll
        for (int e = 0; e < NE_; e++) acc[e] += __shfl_down_sync(0xffffffffu, acc[e], off);
    if (lane == 0) {
        float l0 = -1e30f, l1 = -1e30f; int e0 = 0, e1 = 0;
#pragma unroll
        for (int e = 0; e < NE_; e++) {
            float vv = acc[e] + rtb[e];
            if (vv > l0) { l1 = l0; e1 = e0; l0 = vv; e0 = e; }
            else if (vv > l1) { l1 = vv; e1 = e; }
        }
        float ew = expf(l1 - l0);          // normalized top-2 softmax weights
        float w0 = 1.f/(1.f + ew);
        float w1 = ew/(1.f + ew);
        int p0 = atomicAdd(&g_cnt[e0], 1); g_list[e0*T_ + p0] = t;
        int p1 = atomicAdd(&g_cnt[e1], 1); g_list[e1*T_ + p1] = t;
        g_ebuf[2*t]   = e0; g_pbuf[2*t]   = p0; g_wbuf[2*t]   = w0;
        g_ebuf[2*t+1] = e1; g_pbuf[2*t+1] = p1; g_wbuf[2*t+1] = w1;
    }
}

// ---------------- combine: h += w0*eo[e0,p0] + w1*eo[e1,p1] ----------------
__global__ void combine_kernel() {
    int t = blockIdx.x, d = threadIdx.x;
    float v = g_h[(size_t)t*D_ + d];
#pragma unroll
    for (int kk = 0; kk < 2; kk++) {
        int e = g_ebuf[2*t + kk];
        int p = g_pbuf[2*t + kk];
        float w = g_wbuf[2*t + kk];
        v += w * g_eo[((size_t)e*T_ + p)*D_ + d];
    }
    g_h[(size_t)t*D_ + d] = v;
}

// ---------------- head: LN(last token) -> pred / softplus(unc) ----------------
__global__ void head_kernel(const float* __restrict__ ln_g, const float* __restrict__ ln_b,
                            const float* __restrict__ pw, const float* __restrict__ pb,
                            const float* __restrict__ uw, const float* __restrict__ ub,
                            float* __restrict__ out) {
    __shared__ float red[256];
    __shared__ float norm[256];
    int b = blockIdx.x, d = threadIdx.x;
    float hv = g_h[(size_t)(b*L_ + L_ - 1)*D_ + d];
    red[d] = hv; __syncthreads();
    for (int s = 128; s > 0; s >>= 1) { if (d < s) red[d] += red[d+s]; __syncthreads(); }
    float mu = red[0] * (1.f/256.f);
    __syncthreads();
    float df = hv - mu;
    red[d] = df*df; __syncthreads();
    for (int s = 128; s > 0; s >>= 1) { if (d < s) red[d] += red[d+s]; __syncthreads(); }
    float var = red[0] * (1.f/256.f);
    norm[d] = df * rsqrtf(var + 1e-5f) * ln_g[d] + ln_b[d];
    __syncthreads();
    if (d < 2*NOUT_) {
        int o = d % NOUT_;
        bool un = (d >= NOUT_);
        const float* W = un ? uw : pw;
        float acc = un ? ub[o] : pb[o];
        for (int i = 0; i < D_; i++) acc += norm[i]*W[i*NOUT_ + o];
        if (!un) out[b*NOUT_ + o] = acc;
        else     out[B_*NOUT_ + b*NOUT_ + o] = (acc > 20.f) ? acc : log1pf(expf(acc));
    }
}

// ---------------- launch ----------------
extern "C" void kernel_launch(void* const* d_in, const int* in_sizes, int n_in,
                              void* d_out, int out_size) {
    const float* x     = (const float*)d_in[0];
    const float* emb_w = (const float*)d_in[1];
    const float* emb_b = (const float*)d_in[2];
    const float* wq    = (const float*)d_in[3];
    const float* wk    = (const float*)d_in[4];
    const float* wv    = (const float*)d_in[5];
    const float* wo    = (const float*)d_in[6];
    const float* wfreq = (const float*)d_in[7];
    const float* wph   = (const float*)d_in[8];
    const float* rtw   = (const float*)d_in[9];
    const float* rtb   = (const float*)d_in[10];
    const float* ew1   = (const float*)d_in[11];
    const float* eb1   = (const float*)d_in[12];
    const float* ew2   = (const float*)d_in[13];
    const float* eb2   = (const float*)d_in[14];
    const float* ln_g  = (const float*)d_in[15];
    const float* ln_b  = (const float*)d_in[16];
    const float* pw    = (const float*)d_in[17];
    const float* pb    = (const float*)d_in[18];
    const float* uw    = (const float*)d_in[19];
    const float* ub    = (const float*)d_in[20];
    float* out = (float*)d_out;

    float *ph, *pq, *pk, *pv, *pao, *peo, *phb;
    int *pcnt, *plist;
    cudaGetSymbolAddress((void**)&ph,   g_h);
    cudaGetSymbolAddress((void**)&pq,   g_q);
    cudaGetSymbolAddress((void**)&pk,   g_k);
    cudaGetSymbolAddress((void**)&pv,   g_v);
    cudaGetSymbolAddress((void**)&pao,  g_ao);
    cudaGetSymbolAddress((void**)&peo,  g_eo);
    cudaGetSymbolAddress((void**)&phb,  g_hb);
    cudaGetSymbolAddress((void**)&pcnt, g_cnt);
    cudaGetSymbolAddress((void**)&plist,g_list);

    cudaFuncSetAttribute(attn_kernel, cudaFuncAttributeMaxDynamicSharedMemorySize, ATTN_SMEM);

    embed_kernel<<<T_, D_>>>(x, emb_w, emb_b);

    dim3 gproj(T_/128, D_/128, 1);        // (128, 2)
    for (int i = 0; i < NL_; i++) {
        const float* Wq = wq + (size_t)i*D_*D_;
        const float* Wk = wk + (size_t)i*D_*D_;
        const float* Wv = wv + (size_t)i*D_*D_;
        const float* Wo = wo + (size_t)i*D_*D_;

        mma_gemm<EPI_NONE><<<gproj, 256>>>(ph, D_, 0, Wq, D_, 0, pq, D_, 0,
                                           nullptr, 0, nullptr, nullptr, 0, nullptr,
                                           T_, D_, D_);
        mma_gemm<EPI_NONE><<<gproj, 256>>>(ph, D_, 0, Wk, D_, 0, pk, D_, 0,
                                           nullptr, 0, nullptr, nullptr, 0, nullptr,
                                           T_, D_, D_);
        mma_gemm<EPI_NONE><<<gproj, 256>>>(ph, D_, 0, Wv, D_, 0, pv, D_, 0,
                                           nullptr, 0, nullptr, nullptr, 0, nullptr,
                                           T_, D_, D_);
        attn_kernel<<<B_*H_, L_, ATTN_SMEM>>>(pq, pk, pv, wfreq, wph, pao, i);
        mma_gemm<EPI_RES><<<gproj, 256>>>(pao, D_, 0, Wo, D_, 0, ph, D_, 0,
                                          nullptr, 0, ph, nullptr, 0, nullptr,
                                          T_, D_, D_);   // out proj + residual

        if (i % 2 == 0) {
            int m = i / 2;
            reset_kernel<<<1, 32>>>();
            router_kernel<<<T_/8, 256>>>(rtw + (size_t)m*D_*NE_, rtb + m*NE_);

            // FFN1: per expert, gathered rows of g_h: hb = gelu(x @ w1 + b1)
            dim3 g1(T_/128, DFF_/128, NE_);   // (128, 8, 8)
            mma_gemm<EPI_BIAS_GELU><<<g1, 256>>>(
                ph, D_, 0,
                ew1 + (size_t)m*NE_*D_*DFF_, DFF_, (size_t)D_*DFF_,
                phb, DFF_, (size_t)T_*DFF_,
                eb1 + (size_t)m*NE_*DFF_, DFF_,
                nullptr,
                plist, T_, pcnt,
                T_, DFF_, D_);

            // FFN2: eo = hb @ w2 + b2
            dim3 g2(T_/128, D_/128, NE_);     // (128, 2, 8)
            mma_gemm<EPI_BIAS><<<g2, 256>>>(
                phb, DFF_, (size_t)T_*DFF_,
                ew2 + (size_t)m*NE_*DFF_*D_, D_, (size_t)DFF_*D_,
                peo, D_, (size_t)T_*D_,
                eb2 + (size_t)m*NE_*D_, D_,
                nullptr,
                nullptr, 0, pcnt,
                T_, D_, DFF_);

            combine_kernel<<<T_, D_>>>();
        }
    }
    head_kernel<<<B_, D_>>>(ln_g, ln_b, pw, pb, uw, ub, out);
}

// round 6
// speedup vs baseline: 1.3335x; 1.3335x over previous
#include <cuda_runtime.h>
#include <math.h>
#include <stdint.h>

#define B_ 128
#define L_ 128
#define T_ (B_*L_)
#define DIN_ 6
#define D_ 256
#define H_ 8
#define DK_ 32
#define NL_ 6
#define NE_ 8
#define DFF_ 1024
#define NOUT_ 5

// ---------------- device scratch (no allocations allowed) ----------------
__device__ float g_h[T_*D_];
__device__ float g_q[T_*D_];
__device__ float g_k[T_*D_];
__device__ float g_v[T_*D_];
__device__ float g_ao[T_*D_];
__device__ float g_eo[(size_t)NE_*T_*D_];     // per-expert FFN outputs by list position
__device__ float g_hb[(size_t)NE_*T_*DFF_];   // FFN hidden (gelu output), per (e, pos)
__device__ int   g_cnt[NE_];
__device__ int   g_list[NE_*T_];
__device__ int   g_ebuf[T_*2];
__device__ int   g_pbuf[T_*2];
__device__ float g_wbuf[T_*2];

__device__ __forceinline__ uint32_t f2tf(float x) {
    uint32_t u;
    asm("cvt.rna.tf32.f32 %0, %1;" : "=r"(u) : "f"(x));
    return u;
}

// ---------------- embed: h = x @ emb_w + emb_b ----------------
__global__ void embed_kernel(const float* __restrict__ x,
                             const float* __restrict__ w,
                             const float* __restrict__ b) {
    int t = blockIdx.x, d = threadIdx.x;
    float acc = b[d];
#pragma unroll
    for (int i = 0; i < DIN_; i++) acc += x[t*DIN_ + i] * w[i*D_ + d];
    g_h[(size_t)t*D_ + d] = acc;
}

// ---------------- TF32 tensor-core GEMM ----------------
// C[M,N] = A[M,K] @ W[K,N]  (both row-major), fused epilogues.
// Block tile 128x128, 8 warps (4M x 2N), warp tile 32x64 (2 m16 x 8 n8), K-chunk 32.
#define EPI_NONE      0
#define EPI_RES       1
#define EPI_BIAS_GELU 2
#define EPI_BIAS      3

#define LDA_S 36
#define LDB_S 136

template<int EPI>
__global__ __launch_bounds__(256)
void mma_gemm(const float* __restrict__ A, int lda, size_t strideA,
              const float* __restrict__ W, int ldw, size_t strideW,
              float* __restrict__ C, int ldc, size_t strideC,
              const float* __restrict__ bias, size_t strideBias,
              const float* __restrict__ res,
              const int* __restrict__ gather, size_t strideGather,
              const int* __restrict__ cntPtr,
              int M, int N, int K) {
    __shared__ float As[128*LDA_S];
    __shared__ float Bs[32*LDB_S];

    int e = blockIdx.z;
    const float* Ae = A + (size_t)e*strideA;
    const float* We = W + (size_t)e*strideW;
    float*       Ce = C + (size_t)e*strideC;
    const float* be = bias ? bias + (size_t)e*strideBias : nullptr;
    const int*   ge = gather ? gather + (size_t)e*strideGather : nullptr;
    int Mloc = cntPtr ? cntPtr[e] : M;

    int bm = blockIdx.x * 128;
    if (bm >= Mloc) return;
    int bn = blockIdx.y * 128;

    int tid = threadIdx.x;
    int lane = tid & 31;
    int wid = tid >> 5;
    int wm = wid & 3;        // 0..3  M direction
    int wn = wid >> 2;       // 0..1  N direction

    float acc[2][8][4];
#pragma unroll
    for (int mt = 0; mt < 2; mt++)
#pragma unroll
        for (int nt = 0; nt < 8; nt++)
#pragma unroll
            for (int i = 0; i < 4; i++) acc[mt][nt][i] = 0.f;

    for (int k0 = 0; k0 < K; k0 += 32) {
        // ---- load A tile 128x32 (gathered, guarded) ----
#pragma unroll
        for (int p = 0; p < 4; p++) {
            int f = tid + p*256;
            int r = f >> 3;              // 0..127
            int c4 = (f & 7) << 2;       // 0,4,...,28
            float4 v = make_float4(0.f, 0.f, 0.f, 0.f);
            int grow = bm + r;
            if (grow < Mloc) {
                int arow = ge ? ge[grow] : grow;
                v = *(const float4*)(Ae + (size_t)arow*lda + k0 + c4);
            }
            float* dst = As + r*LDA_S + c4;
            dst[0] = __uint_as_float(f2tf(v.x));
            dst[1] = __uint_as_float(f2tf(v.y));
            dst[2] = __uint_as_float(f2tf(v.z));
            dst[3] = __uint_as_float(f2tf(v.w));
        }
        // ---- load B tile 32x128 ----
#pragma unroll
        for (int p = 0; p < 4; p++) {
            int f = tid + p*256;
            int kr = f >> 5;             // 0..31
            int c4 = (f & 31) << 2;      // 0..124
            float4 v = *(const float4*)(We + (size_t)(k0 + kr)*ldw + bn + c4);
            float* dst = Bs + kr*LDB_S + c4;
            dst[0] = __uint_as_float(f2tf(v.x));
            dst[1] = __uint_as_float(f2tf(v.y));
            dst[2] = __uint_as_float(f2tf(v.z));
            dst[3] = __uint_as_float(f2tf(v.w));
        }
        __syncthreads();

        const float* ar0 = As + (wm*32 + (lane >> 2))*LDA_S + (lane & 3);
        const float* br0 = Bs + (lane & 3)*LDB_S + wn*64 + (lane >> 2);
#pragma unroll
        for (int kk = 0; kk < 32; kk += 8) {
            uint32_t af[2][4];
#pragma unroll
            for (int mt = 0; mt < 2; mt++) {
                const float* ar = ar0 + mt*16*LDA_S + kk;
                af[mt][0] = __float_as_uint(ar[0]);
                af[mt][1] = __float_as_uint(ar[8*LDA_S]);
                af[mt][2] = __float_as_uint(ar[4]);
                af[mt][3] = __float_as_uint(ar[8*LDA_S + 4]);
            }
            uint32_t bf[8][2];
#pragma unroll
            for (int nt = 0; nt < 8; nt++) {
                const float* br = br0 + kk*LDB_S + nt*8;
                bf[nt][0] = __float_as_uint(br[0]);
                bf[nt][1] = __float_as_uint(br[4*LDB_S]);
            }
#pragma unroll
            for (int mt = 0; mt < 2; mt++)
#pragma unroll
                for (int nt = 0; nt < 8; nt++) {
                    asm volatile(
                        "mma.sync.aligned.m16n8k8.row.col.f32.tf32.tf32.f32 "
                        "{%0,%1,%2,%3}, {%4,%5,%6,%7}, {%8,%9}, {%0,%1,%2,%3};"
                        : "+f"(acc[mt][nt][0]), "+f"(acc[mt][nt][1]),
                          "+f"(acc[mt][nt][2]), "+f"(acc[mt][nt][3])
                        : "r"(af[mt][0]), "r"(af[mt][1]), "r"(af[mt][2]), "r"(af[mt][3]),
                          "r"(bf[nt][0]), "r"(bf[nt][1]));
                }
        }
        __syncthreads();
    }

    // ---- epilogue ----
#pragma unroll
    for (int mt = 0; mt < 2; mt++) {
#pragma unroll
        for (int nt = 0; nt < 8; nt++) {
            int r0 = bm + wm*32 + mt*16 + (lane >> 2);
            int c0 = bn + wn*64 + nt*8 + ((lane & 3) << 1);
#pragma unroll
            for (int i = 0; i < 4; i++) {
                int row = r0 + ((i >> 1) << 3);
                int col = c0 + (i & 1);
                if (row < Mloc) {
                    float v = acc[mt][nt][i];
                    if (EPI == EPI_BIAS_GELU) {
                        v += be[col];
                        v = 0.5f*v*(1.f + erff(v*0.7071067811865475f));
                    } else if (EPI == EPI_BIAS) {
                        v += be[col];
                    } else if (EPI == EPI_RES) {
                        v += res[(size_t)row*ldc + col];
                    }
                    Ce[(size_t)row*ldc + col] = v;
                }
            }
        }
    }
}

// ---------------- tensor-core wave attention: one block per (b, head) ----------------
// Phase1: S = Q@K^T via mma (Q as A [m][k], K transposed as B [k=d][n=j]).
// Softmax on register tile (wave*scale folded into wav[]).
// Phase2: O = P@V via mma (P in smem as A [m][k=j], V as B [k=j][n=d]).
#define LDPS 132
#define LDQ  36
#define LDK  136
#define LDV  36
#define OFF_KS  (128*LDQ)                 // 4608
#define OFF_VS  (128*LDPS)                // 16896
#define OFF_WAV (OFF_VS + 128*LDV)        // 21504
#define OFF_RED (OFF_WAV + 128)           // 21632
#define ATT_SMEM ((OFF_RED + 256)*4)      // 87552 bytes

__global__ __launch_bounds__(256)
void attn_mma(const float* __restrict__ q, const float* __restrict__ k,
              const float* __restrict__ v, const float* __restrict__ wfreq,
              const float* __restrict__ wphase, float* __restrict__ out, int layer) {
    extern __shared__ float sm[];
    float* Ps  = sm;             // [128][132]  (phase 2; aliases Qs/Ks)
    float* Qs  = sm;             // [128][36]   (phase 1)
    float* Ks  = sm + OFF_KS;    // [32][136]   (phase 1)
    float* Vs  = sm + OFF_VS;    // [128][36]
    float* wav = sm + OFF_WAV;   // [128] wave*scale, later inv row sums
    float* red = sm + OFF_RED;   // [128][2] cross-warp reductions

    int b = blockIdx.x >> 3, hh = blockIdx.x & 7;
    int tid = threadIdx.x, lane = tid & 31, wid = tid >> 5;
    int wm = wid & 3, wn = wid >> 2;

    const float* qb = q + (size_t)(b*L_)*D_ + hh*DK_;
    const float* kb = k + (size_t)(b*L_)*D_ + hh*DK_;
    const float* vb = v + (size_t)(b*L_)*D_ + hh*DK_;

    if (tid < L_) {
        float fr = wfreq[layer*H_ + hh], ph = wphase[layer*H_ + hh];
        wav[tid] = cosf(6.283185307179586f*fr*(float)tid + ph) * 0.17677669529663688f;
    }

    // ---- load Q[m][d], K^T[d][j], V[j][d] tiles (tf32) ----
#pragma unroll
    for (int p = 0; p < 4; p++) {
        int f = tid + p*256;
        int r = f >> 3;              // 0..127 (m for Q, j for K/V)
        int c4 = (f & 7) << 2;       // d base
        float4 vq = *(const float4*)(qb + (size_t)r*D_ + c4);
        Qs[r*LDQ + c4 + 0] = __uint_as_float(f2tf(vq.x));
        Qs[r*LDQ + c4 + 1] = __uint_as_float(f2tf(vq.y));
        Qs[r*LDQ + c4 + 2] = __uint_as_float(f2tf(vq.z));
        Qs[r*LDQ + c4 + 3] = __uint_as_float(f2tf(vq.w));
        float4 vk = *(const float4*)(kb + (size_t)r*D_ + c4);
        Ks[(c4 + 0)*LDK + r] = __uint_as_float(f2tf(vk.x));
        Ks[(c4 + 1)*LDK + r] = __uint_as_float(f2tf(vk.y));
        Ks[(c4 + 2)*LDK + r] = __uint_as_float(f2tf(vk.z));
        Ks[(c4 + 3)*LDK + r] = __uint_as_float(f2tf(vk.w));
        float4 vv = *(const float4*)(vb + (size_t)r*D_ + c4);
        Vs[r*LDV + c4 + 0] = __uint_as_float(f2tf(vv.x));
        Vs[r*LDV + c4 + 1] = __uint_as_float(f2tf(vv.y));
        Vs[r*LDV + c4 + 2] = __uint_as_float(f2tf(vv.z));
        Vs[r*LDV + c4 + 3] = __uint_as_float(f2tf(vv.w));
    }
    __syncthreads();

    // ---- mma1: scores 128x128, K-dim = 32 ----
    float acc[2][8][4];
#pragma unroll
    for (int mt = 0; mt < 2; mt++)
#pragma unroll
        for (int nt = 0; nt < 8; nt++)
#pragma unroll
            for (int i = 0; i < 4; i++) acc[mt][nt][i] = 0.f;
    {
        const float* ar0 = Qs + (wm*32 + (lane >> 2))*LDQ + (lane & 3);
        const float* br0 = Ks + (lane & 3)*LDK + wn*64 + (lane >> 2);
#pragma unroll
        for (int kk = 0; kk < 32; kk += 8) {
            uint32_t af[2][4];
#pragma unroll
            for (int mt = 0; mt < 2; mt++) {
                const float* ar = ar0 + mt*16*LDQ + kk;
                af[mt][0] = __float_as_uint(ar[0]);
                af[mt][1] = __float_as_uint(ar[8*LDQ]);
                af[mt][2] = __float_as_uint(ar[4]);
                af[mt][3] = __float_as_uint(ar[8*LDQ + 4]);
            }
            uint32_t bf[8][2];
#pragma unroll
            for (int nt = 0; nt < 8; nt++) {
                const float* br = br0 + kk*LDK + nt*8;
                bf[nt][0] = __float_as_uint(br[0]);
                bf[nt][1] = __float_as_uint(br[4*LDK]);
            }
#pragma unroll
            for (int mt = 0; mt < 2; mt++)
#pragma unroll
                for (int nt = 0; nt < 8; nt++) {
                    asm volatile(
                        "mma.sync.aligned.m16n8k8.row.col.f32.tf32.tf32.f32 "
                        "{%0,%1,%2,%3}, {%4,%5,%6,%7}, {%8,%9}, {%0,%1,%2,%3};"
                        : "+f"(acc[mt][nt][0]), "+f"(acc[mt][nt][1]),
                          "+f"(acc[mt][nt][2]), "+f"(acc[mt][nt][3])
                        : "r"(af[mt][0]), "r"(af[mt][1]), "r"(af[mt][2]), "r"(af[mt][3]),
                          "r"(bf[nt][0]), "r"(bf[nt][1]));
                }
        }
    }
    __syncthreads();   // Qs/Ks dead; Ps region reusable after softmax writes

    // ---- wave * scale, row max ----
    float rmax[2][2] = {{-1e30f, -1e30f}, {-1e30f, -1e30f}};
#pragma unroll
    for (int mt = 0; mt < 2; mt++)
#pragma unroll
        for (int nt = 0; nt < 8; nt++)
#pragma unroll
            for (int i = 0; i < 4; i++) {
                int col = wn*64 + nt*8 + ((lane & 3) << 1) + (i & 1);
                float s = acc[mt][nt][i] * wav[col];
                acc[mt][nt][i] = s;
                rmax[mt][i >> 1] = fmaxf(rmax[mt][i >> 1], s);
            }
#pragma unroll
    for (int mt = 0; mt < 2; mt++)
#pragma unroll
        for (int h2 = 0; h2 < 2; h2++) {
            float m = rmax[mt][h2];
            m = fmaxf(m, __shfl_xor_sync(0xffffffffu, m, 1));
            m = fmaxf(m, __shfl_xor_sync(0xffffffffu, m, 2));
            rmax[mt][h2] = m;
        }
    if ((lane & 3) == 0) {
#pragma unroll
        for (int mt = 0; mt < 2; mt++)
#pragma unroll
            for (int h2 = 0; h2 < 2; h2++) {
                int row = wm*32 + mt*16 + (lane >> 2) + 8*h2;
                red[row*2 + wn] = rmax[mt][h2];
            }
    }
    __syncthreads();
    float rm[2][2];
#pragma unroll
    for (int mt = 0; mt < 2; mt++)
#pragma unroll
        for (int h2 = 0; h2 < 2; h2++) {
            int row = wm*32 + mt*16 + (lane >> 2) + 8*h2;
            rm[mt][h2] = fmaxf(red[row*2], red[row*2 + 1]);
        }

    // ---- exp, row sum ----
    float rsum[2][2] = {{0.f, 0.f}, {0.f, 0.f}};
#pragma unroll
    for (int mt = 0; mt < 2; mt++)
#pragma unroll
        for (int nt = 0; nt < 8; nt++)
#pragma unroll
            for (int i = 0; i < 4; i++) {
                float e = __expf(acc[mt][nt][i] - rm[mt][i >> 1]);
                acc[mt][nt][i] = e;
                rsum[mt][i >> 1] += e;
            }
#pragma unroll
    for (int mt = 0; mt < 2; mt++)
#pragma unroll
        for (int h2 = 0; h2 < 2; h2++) {
            float s = rsum[mt][h2];
            s += __shfl_xor_sync(0xffffffffu, s, 1);
            s += __shfl_xor_sync(0xffffffffu, s, 2);
            rsum[mt][h2] = s;
        }
    __syncthreads();   // max reads done; red reusable for sums
    if ((lane & 3) == 0) {
#pragma unroll
        for (int mt = 0; mt < 2; mt++)
#pragma unroll
            for (int h2 = 0; h2 < 2; h2++) {
                int row = wm*32 + mt*16 + (lane >> 2) + 8*h2;
                red[row*2 + wn] = rsum[mt][h2];
            }
    }
    __syncthreads();
    // inverse row sums -> wav (wav dead), and P -> Ps (tf32)
    if (wn == 0 && (lane & 3) == 0) {
#pragma unroll
        for (int mt = 0; mt < 2; mt++)
#pragma unroll
            for (int h2 = 0; h2 < 2; h2++) {
                int row = wm*32 + mt*16 + (lane >> 2) + 8*h2;
                wav[row] = 1.f / (red[row*2] + red[row*2 + 1]);
            }
    }
#pragma unroll
    for (int mt = 0; mt < 2; mt++)
#pragma unroll
        for (int nt = 0; nt < 8; nt++)
#pragma unroll
            for (int i = 0; i < 4; i++) {
                int row = wm*32 + mt*16 + (lane >> 2) + 8*(i >> 1);
                int col = wn*64 + nt*8 + ((lane & 3) << 1) + (i & 1);
                Ps[row*LDPS + col] = __uint_as_float(f2tf(acc[mt][nt][i]));
            }
    __syncthreads();

    // ---- mma2: O = P @ V, 8 warps over M (16 rows each), N=32, K=128 ----
    float o[4][4];
#pragma unroll
    for (int nt = 0; nt < 4; nt++)
#pragma unroll
        for (int i = 0; i < 4; i++) o[nt][i] = 0.f;
    {
        const float* ar2 = Ps + (wid*16 + (lane >> 2))*LDPS + (lane & 3);
        const float* br2 = Vs + (lane & 3)*LDV + (lane >> 2);
#pragma unroll
        for (int kk = 0; kk < 128; kk += 8) {
            uint32_t af[4];
            af[0] = __float_as_uint(ar2[kk]);
            af[1] = __float_as_uint(ar2[8*LDPS + kk]);
            af[2] = __float_as_uint(ar2[kk + 4]);
            af[3] = __float_as_uint(ar2[8*LDPS + kk + 4]);
#pragma unroll
            for (int nt = 0; nt < 4; nt++) {
                uint32_t b0 = __float_as_uint(br2[kk*LDV + nt*8]);
                uint32_t b1 = __float_as_uint(br2[(kk + 4)*LDV + nt*8]);
                asm volatile(
                    "mma.sync.aligned.m16n8k8.row.col.f32.tf32.tf32.f32 "
                    "{%0,%1,%2,%3}, {%4,%5,%6,%7}, {%8,%9}, {%0,%1,%2,%3};"
                    : "+f"(o[nt][0]), "+f"(o[nt][1]), "+f"(o[nt][2]), "+f"(o[nt][3])
                    : "r"(af[0]), "r"(af[1]), "r"(af[2]), "r"(af[3]),
                      "r"(b0), "r"(b1));
            }
        }
    }

    // ---- epilogue: normalize by row sum, store ----
    float is0 = wav[wid*16 + (lane >> 2)];
    float is1 = wav[wid*16 + (lane >> 2) + 8];
#pragma unroll
    for (int nt = 0; nt < 4; nt++)
#pragma unroll
        for (int i = 0; i < 4; i++) {
            int row = wid*16 + (lane >> 2) + 8*(i >> 1);
            int col = nt*8 + ((lane & 3) << 1) + (i & 1);
            out[(size_t)(b*L_ + row)*D_ + hh*DK_ + col] = o[nt][i] * ((i >> 1) ? is1 : is0);
        }
}

// ---------------- MoE router + bucketing (one warp per token) ----------------
__global__ void reset_kernel() {
    if (threadIdx.x < NE_) g_cnt[threadIdx.x] = 0;
}

__global__ void router_kernel(const float* __restrict__ rtw, const float* __restrict__ rtb) {
    int lane = threadIdx.x & 31;
    int t = blockIdx.x*8 + (threadIdx.x >> 5);
    const float* xr = g_h + (size_t)t*D_;
    float acc[NE_];
#pragma unroll
    for (int e = 0; e < NE_; e++) acc[e] = 0.f;
    for (int d = lane; d < D_; d += 32) {
        float xv = xr[d];
#pragma unroll
        for (int e = 0; e < NE_; e++) acc[e] += xv * rtw[d*NE_ + e];
    }
#pragma unroll
    for (int off = 16; off > 0; off >>= 1)
#pragma unroll
        for (int e = 0; e < NE_; e++) acc[e] += __shfl_down_sync(0xffffffffu, acc[e], off);
    if (lane == 0) {
        float l0 = -1e30f, l1 = -1e30f; int e0 = 0, e1 = 0;
#pragma unroll
        for (int e = 0; e < NE_; e++) {
            float vv = acc[e] + rtb[e];
            if (vv > l0) { l1 = l0; e1 = e0; l0 = vv; e0 = e; }
            else if (vv > l1) { l1 = vv; e1 = e; }
        }
        float ew = expf(l1 - l0);          // normalized top-2 softmax weights
        float w0 = 1.f/(1.f + ew);
        float w1 = ew/(1.f + ew);
        int p0 = atomicAdd(&g_cnt[e0], 1); g_list[e0*T_ + p0] = t;
        int p1 = atomicAdd(&g_cnt[e1], 1); g_list[e1*T_ + p1] = t;
        g_ebuf[2*t]   = e0; g_pbuf[2*t]   = p0; g_wbuf[2*t]   = w0;
        g_ebuf[2*t+1] = e1; g_pbuf[2*t+1] = p1; g_wbuf[2*t+1] = w1;
    }
}

// ---------------- combine: h += w0*eo[e0,p0] + w1*eo[e1,p1] ----------------
__global__ void combine_kernel() {
    int t = blockIdx.x, d = threadIdx.x;
    float v = g_h[(size_t)t*D_ + d];
#pragma unroll
    for (int kk = 0; kk < 2; kk++) {
        int e = g_ebuf[2*t + kk];
        int p = g_pbuf[2*t + kk];
        float w = g_wbuf[2*t + kk];
        v += w * g_eo[((size_t)e*T_ + p)*D_ + d];
    }
    g_h[(size_t)t*D_ + d] = v;
}

// ---------------- head: LN(last token) -> pred / softplus(unc) ----------------
__global__ void head_kernel(const float* __restrict__ ln_g, const float* __restrict__ ln_b,
                            const float* __restrict__ pw, const float* __restrict__ pb,
                            const float* __restrict__ uw, const float* __restrict__ ub,
                            float* __restrict__ out) {
    __shared__ float red[256];
    __shared__ float norm[256];
    int b = blockIdx.x, d = threadIdx.x;
    float hv = g_h[(size_t)(b*L_ + L_ - 1)*D_ + d];
    red[d] = hv; __syncthreads();
    for (int s = 128; s > 0; s >>= 1) { if (d < s) red[d] += red[d+s]; __syncthreads(); }
    float mu = red[0] * (1.f/256.f);
    __syncthreads();
    float df = hv - mu;
    red[d] = df*df; __syncthreads();
    for (int s = 128; s > 0; s >>= 1) { if (d < s) red[d] += red[d+s]; __syncthreads(); }
    float var = red[0] * (1.f/256.f);
    norm[d] = df * rsqrtf(var + 1e-5f) * ln_g[d] + ln_b[d];
    __syncthreads();
    if (d < 2*NOUT_) {
        int o = d % NOUT_;
        bool un = (d >= NOUT_);
        const float* W = un ? uw : pw;
        float acc = un ? ub[o] : pb[o];
        for (int i = 0; i < D_; i++) acc += norm[i]*W[i*NOUT_ + o];
        if (!un) out[b*NOUT_ + o] = acc;
        else     out[B_*NOUT_ + b*NOUT_ + o] = (acc > 20.f) ? acc : log1pf(expf(acc));
    }
}

// ---------------- launch ----------------
extern "C" void kernel_launch(void* const* d_in, const int* in_sizes, int n_in,
                              void* d_out, int out_size) {
    const float* x     = (const float*)d_in[0];
    const float* emb_w = (const float*)d_in[1];
    const float* emb_b = (const float*)d_in[2];
    const float* wq    = (const float*)d_in[3];
    const float* wk    = (const float*)d_in[4];
    const float* wv    = (const float*)d_in[5];
    const float* wo    = (const float*)d_in[6];
    const float* wfreq = (const float*)d_in[7];
    const float* wph   = (const float*)d_in[8];
    const float* rtw   = (const float*)d_in[9];
    const float* rtb   = (const float*)d_in[10];
    const float* ew1   = (const float*)d_in[11];
    const float* eb1   = (const float*)d_in[12];
    const float* ew2   = (const float*)d_in[13];
    const float* eb2   = (const float*)d_in[14];
    const float* ln_g  = (const float*)d_in[15];
    const float* ln_b  = (const float*)d_in[16];
    const float* pw    = (const float*)d_in[17];
    const float* pb    = (const float*)d_in[18];
    const float* uw    = (const float*)d_in[19];
    const float* ub    = (const float*)d_in[20];
    float* out = (float*)d_out;

    float *ph, *pq, *pk, *pv, *pao, *peo, *phb;
    int *pcnt, *plist;
    cudaGetSymbolAddress((void**)&ph,   g_h);
    cudaGetSymbolAddress((void**)&pq,   g_q);
    cudaGetSymbolAddress((void**)&pk,   g_k);
    cudaGetSymbolAddress((void**)&pv,   g_v);
    cudaGetSymbolAddress((void**)&pao,  g_ao);
    cudaGetSymbolAddress((void**)&peo,  g_eo);
    cudaGetSymbolAddress((void**)&phb,  g_hb);
    cudaGetSymbolAddress((void**)&pcnt, g_cnt);
    cudaGetSymbolAddress((void**)&plist,g_list);

    cudaFuncSetAttribute(attn_mma, cudaFuncAttributeMaxDynamicSharedMemorySize, ATT_SMEM);

    embed_kernel<<<T_, D_>>>(x, emb_w, emb_b);

    dim3 gproj(T_/128, D_/128, 1);        // (128, 2)
    for (int i = 0; i < NL_; i++) {
        const float* Wq = wq + (size_t)i*D_*D_;
        const float* Wk = wk + (size_t)i*D_*D_;
        const float* Wv = wv + (size_t)i*D_*D_;
        const float* Wo = wo + (size_t)i*D_*D_;

        mma_gemm<EPI_NONE><<<gproj, 256>>>(ph, D_, 0, Wq, D_, 0, pq, D_, 0,
                                           nullptr, 0, nullptr, nullptr, 0, nullptr,
                                           T_, D_, D_);
        mma_gemm<EPI_NONE><<<gproj, 256>>>(ph, D_, 0, Wk, D_, 0, pk, D_, 0,
                                           nullptr, 0, nullptr, nullptr, 0, nullptr,
                                           T_, D_, D_);
        mma_gemm<EPI_NONE><<<gproj, 256>>>(ph, D_, 0, Wv, D_, 0, pv, D_, 0,
                                           nullptr, 0, nullptr, nullptr, 0, nullptr,
                                           T_, D_, D_);
        attn_mma<<<B_*H_, 256, ATT_SMEM>>>(pq, pk, pv, wfreq, wph, pao, i);
        mma_gemm<EPI_RES><<<gproj, 256>>>(pao, D_, 0, Wo, D_, 0, ph, D_, 0,
                                          nullptr, 0, ph, nullptr, 0, nullptr,
                                          T_, D_, D_);   // out proj + residual

        if (i % 2 == 0) {
            int m = i / 2;
            reset_kernel<<<1, 32>>>();
            router_kernel<<<T_/8, 256>>>(rtw + (size_t)m*D_*NE_, rtb + m*NE_);

            // FFN1: per expert, gathered rows of g_h: hb = gelu(x @ w1 + b1)
            dim3 g1(T_/128, DFF_/128, NE_);   // (128, 8, 8)
            mma_gemm<EPI_BIAS_GELU><<<g1, 256>>>(
                ph, D_, 0,
                ew1 + (size_t)m*NE_*D_*DFF_, DFF_, (size_t)D_*DFF_,
                phb, DFF_, (size_t)T_*DFF_,
                eb1 + (size_t)m*NE_*DFF_, DFF_,
                nullptr,
                plist, T_, pcnt,
                T_, DFF_, D_);

            // FFN2: eo = hb @ w2 + b2
            dim3 g2(T_/128, D_/128, NE_);     // (128, 2, 8)
            mma_gemm<EPI_BIAS><<<g2, 256>>>(
                phb, DFF_, (size_t)T_*DFF_,
                ew2 + (size_t)m*NE_*DFF_*D_, D_, (size_t)DFF_*D_,
                peo, D_, (size_t)T_*D_,
                eb2 + (size_t)m*NE_*D_, D_,
                nullptr,
                nullptr, 0, pcnt,
                T_, D_, DFF_);

            combine_kernel<<<T_, D_>>>();
        }
    }
    head_kernel<<<B_, D_>>>(ln_g, ln_b, pw, pb, uw, ub, out);
}

// round 7
// speedup vs baseline: 1.8609x; 1.3955x over previous
#include <cuda_runtime.h>
#include <math.h>
#include <stdint.h>

#define B_ 128
#define L_ 128
#define T_ (B_*L_)
#define DIN_ 6
#define D_ 256
#define H_ 8
#define DK_ 32
#define NL_ 6
#define NE_ 8
#define DFF_ 1024
#define NOUT_ 5

// ---------------- device scratch (no allocations allowed) ----------------
__device__ float g_h[T_*D_];
__device__ float g_q[T_*D_];
__device__ float g_k[T_*D_];
__device__ float g_v[T_*D_];
__device__ float g_ao[T_*D_];
__device__ float g_eo[(size_t)NE_*T_*D_];     // per-expert FFN outputs by list position
__device__ float g_hb[(size_t)NE_*T_*DFF_];   // FFN hidden (gelu output), per (e, pos)
__device__ int   g_cnt[NE_];
__device__ int   g_list[NE_*T_];
__device__ int   g_ebuf[T_*2];
__device__ int   g_pbuf[T_*2];
__device__ float g_wbuf[T_*2];

__device__ __forceinline__ uint32_t f2tf(float x) {
    uint32_t u;
    asm("cvt.rna.tf32.f32 %0, %1;" : "=r"(u) : "f"(x));
    return u;
}

// ---------------- embed: h = x @ emb_w + emb_b ----------------
__global__ void embed_kernel(const float* __restrict__ x,
                             const float* __restrict__ w,
                             const float* __restrict__ b) {
    int t = blockIdx.x, d = threadIdx.x;
    float acc = b[d];
#pragma unroll
    for (int i = 0; i < DIN_; i++) acc += x[t*DIN_ + i] * w[i*D_ + d];
    g_h[(size_t)t*D_ + d] = acc;
}

// ---------------- TF32 tensor-core GEMM, cp.async double-buffered ----------------
// C[M,N] = A[M,K] @ W[K,N]  (both row-major), fused epilogues.
// Block tile 128x128, 8 warps (4M x 2N), warp tile 32x64, K-chunk 32, 2-stage pipeline.
// NOTE: operands are fed to mma.tf32 as raw fp32 (hardware truncates low mantissa bits).
#define EPI_NONE      0
#define EPI_RES       1
#define EPI_BIAS_GELU 2
#define EPI_BIAS      3

#define LDA_S 36
#define LDB_S 136
#define A_ST (128*LDA_S)
#define B_ST (32*LDB_S)
#define GEMM_SMEM ((2*A_ST + 2*B_ST)*4)   // 71680 bytes

template<int EPI>
__global__ __launch_bounds__(256, 2)
void mma_gemm(const float* __restrict__ A, int lda, size_t strideA,
              const float* __restrict__ W, const float* __restrict__ W2,
              const float* __restrict__ W3, int ldw, size_t strideW,
              float* __restrict__ C, float* __restrict__ C2, float* __restrict__ C3,
              int ldc, size_t strideC,
              const float* __restrict__ bias, size_t strideBias,
              const float* __restrict__ res,
              const int* __restrict__ gather, size_t strideGather,
              const int* __restrict__ cntPtr,
              int M, int N, int K, int qkv) {
    extern __shared__ float sm[];
    float* Asb[2] = { sm,            sm + A_ST };
    float* Bsb[2] = { sm + 2*A_ST,   sm + 2*A_ST + B_ST };

    int e = blockIdx.z;
    const float* Ae = A;
    const float* We;
    float*       Ce;
    const float* be = nullptr;
    const int*   ge = nullptr;
    int Mloc = M;
    if (qkv) {
        We = (e == 0) ? W : (e == 1) ? W2 : W3;
        Ce = (e == 0) ? C : (e == 1) ? C2 : C3;
    } else {
        Ae = A + (size_t)e*strideA;
        We = W + (size_t)e*strideW;
        Ce = C + (size_t)e*strideC;
        if (bias)   be = bias + (size_t)e*strideBias;
        if (gather) ge = gather + (size_t)e*strideGather;
        if (cntPtr) Mloc = cntPtr[e];
    }

    int bm = blockIdx.x * 128;
    if (bm >= Mloc) return;
    int bn = blockIdx.y * 128;

    int tid = threadIdx.x;
    int lane = tid & 31;
    int wid = tid >> 5;
    int wm = wid & 3;        // 0..3  M direction
    int wn = wid >> 2;       // 0..1  N direction

    // ---- precompute per-thread load descriptors (k0-independent) ----
    const float* asrc[4]; int apred[4]; int aoff[4];
    const float* bsrc[4]; int boff[4];
#pragma unroll
    for (int p = 0; p < 4; p++) {
        int f = tid + p*256;
        int r = f >> 3, c4 = (f & 7) << 2;
        int grow = bm + r;
        apred[p] = (grow < Mloc) ? 16 : 0;
        int gc = (grow < Mloc) ? grow : (Mloc - 1);
        int arow = ge ? ge[gc] : gc;
        asrc[p] = Ae + (size_t)arow*lda + c4;
        aoff[p] = r*LDA_S + c4;
        int kr = f >> 5, d4 = (f & 31) << 2;
        bsrc[p] = We + (size_t)kr*ldw + bn + d4;
        boff[p] = kr*LDB_S + d4;
    }
    uint32_t sA[2] = { (uint32_t)__cvta_generic_to_shared(Asb[0]),
                       (uint32_t)__cvta_generic_to_shared(Asb[1]) };
    uint32_t sB[2] = { (uint32_t)__cvta_generic_to_shared(Bsb[0]),
                       (uint32_t)__cvta_generic_to_shared(Bsb[1]) };

    auto load_stage = [&](int st, int k0) {
#pragma unroll
        for (int p = 0; p < 4; p++) {
            uint32_t da = sA[st] + (uint32_t)(aoff[p]*4);
            asm volatile("cp.async.ca.shared.global [%0], [%1], 16, %2;"
                         :: "r"(da), "l"(asrc[p] + k0), "r"(apred[p]));
        }
#pragma unroll
        for (int p = 0; p < 4; p++) {
            uint32_t db = sB[st] + (uint32_t)(boff[p]*4);
            asm volatile("cp.async.ca.shared.global [%0], [%1], 16;"
                         :: "r"(db), "l"(bsrc[p] + (size_t)k0*ldw));
        }
        asm volatile("cp.async.commit_group;");
    };

    float acc[2][8][4];
#pragma unroll
    for (int mt = 0; mt < 2; mt++)
#pragma unroll
        for (int nt = 0; nt < 8; nt++)
#pragma unroll
            for (int i = 0; i < 4; i++) acc[mt][nt][i] = 0.f;

    int nk = K >> 5;
    load_stage(0, 0);

    for (int ki = 0; ki < nk; ki++) {
        if (ki + 1 < nk) {
            load_stage((ki + 1) & 1, (ki + 1) << 5);
            asm volatile("cp.async.wait_group 1;");
        } else {
            asm volatile("cp.async.wait_group 0;");
        }
        __syncthreads();

        int st = ki & 1;
        const float* ar0 = Asb[st] + (wm*32 + (lane >> 2))*LDA_S + (lane & 3);
        const float* br0 = Bsb[st] + (lane & 3)*LDB_S + wn*64 + (lane >> 2);
#pragma unroll
        for (int kk = 0; kk < 32; kk += 8) {
            uint32_t af[2][4];
#pragma unroll
            for (int mt = 0; mt < 2; mt++) {
                const float* ar = ar0 + mt*16*LDA_S + kk;
                af[mt][0] = __float_as_uint(ar[0]);
                af[mt][1] = __float_as_uint(ar[8*LDA_S]);
                af[mt][2] = __float_as_uint(ar[4]);
                af[mt][3] = __float_as_uint(ar[8*LDA_S + 4]);
            }
            uint32_t bf[8][2];
#pragma unroll
            for (int nt = 0; nt < 8; nt++) {
                const float* br = br0 + kk*LDB_S + nt*8;
                bf[nt][0] = __float_as_uint(br[0]);
                bf[nt][1] = __float_as_uint(br[4*LDB_S]);
            }
#pragma unroll
            for (int mt = 0; mt < 2; mt++)
#pragma unroll
                for (int nt = 0; nt < 8; nt++) {
                    asm volatile(
                        "mma.sync.aligned.m16n8k8.row.col.f32.tf32.tf32.f32 "
                        "{%0,%1,%2,%3}, {%4,%5,%6,%7}, {%8,%9}, {%0,%1,%2,%3};"
                        : "+f"(acc[mt][nt][0]), "+f"(acc[mt][nt][1]),
                          "+f"(acc[mt][nt][2]), "+f"(acc[mt][nt][3])
                        : "r"(af[mt][0]), "r"(af[mt][1]), "r"(af[mt][2]), "r"(af[mt][3]),
                          "r"(bf[nt][0]), "r"(bf[nt][1]));
                }
        }
        __syncthreads();
    }

    // ---- epilogue ----
#pragma unroll
    for (int mt = 0; mt < 2; mt++) {
#pragma unroll
        for (int nt = 0; nt < 8; nt++) {
            int r0 = bm + wm*32 + mt*16 + (lane >> 2);
            int c0 = bn + wn*64 + nt*8 + ((lane & 3) << 1);
#pragma unroll
            for (int i = 0; i < 4; i++) {
                int row = r0 + ((i >> 1) << 3);
                int col = c0 + (i & 1);
                if (row < Mloc) {
                    float v = acc[mt][nt][i];
                    if (EPI == EPI_BIAS_GELU) {
                        v += be[col];
                        v = 0.5f*v*(1.f + erff(v*0.7071067811865475f));
                    } else if (EPI == EPI_BIAS) {
                        v += be[col];
                    } else if (EPI == EPI_RES) {
                        v += res[(size_t)row*ldc + col];
                    }
                    Ce[(size_t)row*ldc + col] = v;
                }
            }
        }
    }
}

// ---------------- tensor-core wave attention: one block per (b, head) ----------------
#define LDPS 132
#define LDQ  36
#define LDK  136
#define LDV  36
#define OFF_KS  (128*LDQ)                 // 4608
#define OFF_VS  (128*LDPS)                // 16896
#define OFF_WAV (OFF_VS + 128*LDV)        // 21504
#define OFF_RED (OFF_WAV + 128)           // 21632
#define ATT_SMEM ((OFF_RED + 256)*4)      // 87552 bytes

__global__ __launch_bounds__(256)
void attn_mma(const float* __restrict__ q, const float* __restrict__ k,
              const float* __restrict__ v, const float* __restrict__ wfreq,
              const float* __restrict__ wphase, float* __restrict__ out, int layer) {
    extern __shared__ float sm[];
    float* Ps  = sm;             // [128][132]  (phase 2; aliases Qs/Ks)
    float* Qs  = sm;             // [128][36]   (phase 1)
    float* Ks  = sm + OFF_KS;    // [32][136]   (phase 1)
    float* Vs  = sm + OFF_VS;    // [128][36]
    float* wav = sm + OFF_WAV;   // [128] wave*scale, later inv row sums
    float* red = sm + OFF_RED;   // [128][2] cross-warp reductions

    int b = blockIdx.x >> 3, hh = blockIdx.x & 7;
    int tid = threadIdx.x, lane = tid & 31, wid = tid >> 5;
    int wm = wid & 3, wn = wid >> 2;

    const float* qb = q + (size_t)(b*L_)*D_ + hh*DK_;
    const float* kb = k + (size_t)(b*L_)*D_ + hh*DK_;
    const float* vb = v + (size_t)(b*L_)*D_ + hh*DK_;

    if (tid < L_) {
        float fr = wfreq[layer*H_ + hh], ph = wphase[layer*H_ + hh];
        wav[tid] = cosf(6.283185307179586f*fr*(float)tid + ph) * 0.17677669529663688f;
    }

    // ---- load Q[m][d], K^T[d][j], V[j][d] tiles (tf32) ----
#pragma unroll
    for (int p = 0; p < 4; p++) {
        int f = tid + p*256;
        int r = f >> 3;              // 0..127 (m for Q, j for K/V)
        int c4 = (f & 7) << 2;       // d base
        float4 vq = *(const float4*)(qb + (size_t)r*D_ + c4);
        Qs[r*LDQ + c4 + 0] = __uint_as_float(f2tf(vq.x));
        Qs[r*LDQ + c4 + 1] = __uint_as_float(f2tf(vq.y));
        Qs[r*LDQ + c4 + 2] = __uint_as_float(f2tf(vq.z));
        Qs[r*LDQ + c4 + 3] = __uint_as_float(f2tf(vq.w));
        float4 vk = *(const float4*)(kb + (size_t)r*D_ + c4);
        Ks[(c4 + 0)*LDK + r] = __uint_as_float(f2tf(vk.x));
        Ks[(c4 + 1)*LDK + r] = __uint_as_float(f2tf(vk.y));
        Ks[(c4 + 2)*LDK + r] = __uint_as_float(f2tf(vk.z));
        Ks[(c4 + 3)*LDK + r] = __uint_as_float(f2tf(vk.w));
        float4 vv = *(const float4*)(vb + (size_t)r*D_ + c4);
        Vs[r*LDV + c4 + 0] = __uint_as_float(f2tf(vv.x));
        Vs[r*LDV + c4 + 1] = __uint_as_float(f2tf(vv.y));
        Vs[r*LDV + c4 + 2] = __uint_as_float(f2tf(vv.z));
        Vs[r*LDV + c4 + 3] = __uint_as_float(f2tf(vv.w));
    }
    __syncthreads();

    // ---- mma1: scores 128x128, K-dim = 32 ----
    float acc[2][8][4];
#pragma unroll
    for (int mt = 0; mt < 2; mt++)
#pragma unroll
        for (int nt = 0; nt < 8; nt++)
#pragma unroll
            for (int i = 0; i < 4; i++) acc[mt][nt][i] = 0.f;
    {
        const float* ar0 = Qs + (wm*32 + (lane >> 2))*LDQ + (lane & 3);
        const float* br0 = Ks + (lane & 3)*LDK + wn*64 + (lane >> 2);
#pragma unroll
        for (int kk = 0; kk < 32; kk += 8) {
            uint32_t af[2][4];
#pragma unroll
            for (int mt = 0; mt < 2; mt++) {
                const float* ar = ar0 + mt*16*LDQ + kk;
                af[mt][0] = __float_as_uint(ar[0]);
                af[mt][1] = __float_as_uint(ar[8*LDQ]);
                af[mt][2] = __float_as_uint(ar[4]);
                af[mt][3] = __float_as_uint(ar[8*LDQ + 4]);
            }
            uint32_t bf[8][2];
#pragma unroll
            for (int nt = 0; nt < 8; nt++) {
                const float* br = br0 + kk*LDK + nt*8;
                bf[nt][0] = __float_as_uint(br[0]);
                bf[nt][1] = __float_as_uint(br[4*LDK]);
            }
#pragma unroll
            for (int mt = 0; mt < 2; mt++)
#pragma unroll
                for (int nt = 0; nt < 8; nt++) {
                    asm volatile(
                        "mma.sync.aligned.m16n8k8.row.col.f32.tf32.tf32.f32 "
                        "{%0,%1,%2,%3}, {%4,%5,%6,%7}, {%8,%9}, {%0,%1,%2,%3};"
                        : "+f"(acc[mt][nt][0]), "+f"(acc[mt][nt][1]),
                          "+f"(acc[mt][nt][2]), "+f"(acc[mt][nt][3])
                        : "r"(af[mt][0]), "r"(af[mt][1]), "r"(af[mt][2]), "r"(af[mt][3]),
                          "r"(bf[nt][0]), "r"(bf[nt][1]));
                }
        }
    }
    __syncthreads();   // Qs/Ks dead; Ps region reusable after softmax writes

    // ---- wave * scale, row max ----
    float rmax[2][2] = {{-1e30f, -1e30f}, {-1e30f, -1e30f}};
#pragma unroll
    for (int mt = 0; mt < 2; mt++)
#pragma unroll
        for (int nt = 0; nt < 8; nt++)
#pragma unroll
            for (int i = 0; i < 4; i++) {
                int col = wn*64 + nt*8 + ((lane & 3) << 1) + (i & 1);
                float s = acc[mt][nt][i] * wav[col];
                acc[mt][nt][i] = s;
                rmax[mt][i >> 1] = fmaxf(rmax[mt][i >> 1], s);
            }
#pragma unroll
    for (int mt = 0; mt < 2; mt++)
#pragma unroll
        for (int h2 = 0; h2 < 2; h2++) {
            float m = rmax[mt][h2];
            m = fmaxf(m, __shfl_xor_sync(0xffffffffu, m, 1));
            m = fmaxf(m, __shfl_xor_sync(0xffffffffu, m, 2));
            rmax[mt][h2] = m;
        }
    if ((lane & 3) == 0) {
#pragma unroll
        for (int mt = 0; mt < 2; mt++)
#pragma unroll
            for (int h2 = 0; h2 < 2; h2++) {
                int row = wm*32 + mt*16 + (lane >> 2) + 8*h2;
                red[row*2 + wn] = rmax[mt][h2];
            }
    }
    __syncthreads();
    float rm[2][2];
#pragma unroll
    for (int mt = 0; mt < 2; mt++)
#pragma unroll
        for (int h2 = 0; h2 < 2; h2++) {
            int row = wm*32 + mt*16 + (lane >> 2) + 8*h2;
            rm[mt][h2] = fmaxf(red[row*2], red[row*2 + 1]);
        }

    // ---- exp, row sum ----
    float rsum[2][2] = {{0.f, 0.f}, {0.f, 0.f}};
#pragma unroll
    for (int mt = 0; mt < 2; mt++)
#pragma unroll
        for (int nt = 0; nt < 8; nt++)
#pragma unroll
            for (int i = 0; i < 4; i++) {
                float e = __expf(acc[mt][nt][i] - rm[mt][i >> 1]);
                acc[mt][nt][i] = e;
                rsum[mt][i >> 1] += e;
            }
#pragma unroll
    for (int mt = 0; mt < 2; mt++)
#pragma unroll
        for (int h2 = 0; h2 < 2; h2++) {
            float s = rsum[mt][h2];
            s += __shfl_xor_sync(0xffffffffu, s, 1);
            s += __shfl_xor_sync(0xffffffffu, s, 2);
            rsum[mt][h2] = s;
        }
    __syncthreads();   // max reads done; red reusable for sums
    if ((lane & 3) == 0) {
#pragma unroll
        for (int mt = 0; mt < 2; mt++)
#pragma unroll
            for (int h2 = 0; h2 < 2; h2++) {
                int row = wm*32 + mt*16 + (lane >> 2) + 8*h2;
                red[row*2 + wn] = rsum[mt][h2];
            }
    }
    __syncthreads();
    // inverse row sums -> wav (wav dead), and P -> Ps (tf32)
    if (wn == 0 && (lane & 3) == 0) {
#pragma unroll
        for (int mt = 0; mt < 2; mt++)
#pragma unroll
            for (int h2 = 0; h2 < 2; h2++) {
                int row = wm*32 + mt*16 + (lane >> 2) + 8*h2;
                wav[row] = 1.f / (red[row*2] + red[row*2 + 1]);
            }
    }
#pragma unroll
    for (int mt = 0; mt < 2; mt++)
#pragma unroll
        for (int nt = 0; nt < 8; nt++)
#pragma unroll
            for (int i = 0; i < 4; i++) {
                int row = wm*32 + mt*16 + (lane >> 2) + 8*(i >> 1);
                int col = wn*64 + nt*8 + ((lane & 3) << 1) + (i & 1);
                Ps[row*LDPS + col] = __uint_as_float(f2tf(acc[mt][nt][i]));
            }
    __syncthreads();

    // ---- mma2: O = P @ V, 8 warps over M (16 rows each), N=32, K=128 ----
    float o[4][4];
#pragma unroll
    for (int nt = 0; nt < 4; nt++)
#pragma unroll
        for (int i = 0; i < 4; i++) o[nt][i] = 0.f;
    {
        const float* ar2 = Ps + (wid*16 + (lane >> 2))*LDPS + (lane & 3);
        const float* br2 = Vs + (lane & 3)*LDV + (lane >> 2);
#pragma unroll
        for (int kk = 0; kk < 128; kk += 8) {
            uint32_t af[4];
            af[0] = __float_as_uint(ar2[kk]);
            af[1] = __float_as_uint(ar2[8*LDPS + kk]);
            af[2] = __float_as_uint(ar2[kk + 4]);
            af[3] = __float_as_uint(ar2[8*LDPS + kk + 4]);
#pragma unroll
            for (int nt = 0; nt < 4; nt++) {
                uint32_t b0 = __float_as_uint(br2[kk*LDV + nt*8]);
                uint32_t b1 = __float_as_uint(br2[(kk + 4)*LDV + nt*8]);
                asm volatile(
                    "mma.sync.aligned.m16n8k8.row.col.f32.tf32.tf32.f32 "
                    "{%0,%1,%2,%3}, {%4,%5,%6,%7}, {%8,%9}, {%0,%1,%2,%3};"
                    : "+f"(o[nt][0]), "+f"(o[nt][1]), "+f"(o[nt][2]), "+f"(o[nt][3])
                    : "r"(af[0]), "r"(af[1]), "r"(af[2]), "r"(af[3]),
                      "r"(b0), "r"(b1));
            }
        }
    }

    // ---- epilogue: normalize by row sum, store ----
    float is0 = wav[wid*16 + (lane >> 2)];
    float is1 = wav[wid*16 + (lane >> 2) + 8];
#pragma unroll
    for (int nt = 0; nt < 4; nt++)
#pragma unroll
        for (int i = 0; i < 4; i++) {
            int row = wid*16 + (lane >> 2) + 8*(i >> 1);
            int col = nt*8 + ((lane & 3) << 1) + (i & 1);
            out[(size_t)(b*L_ + row)*D_ + hh*DK_ + col] = o[nt][i] * ((i >> 1) ? is1 : is0);
        }
}

// ---------------- MoE router + bucketing (one warp per token) ----------------
__global__ void reset_kernel() {
    if (threadIdx.x < NE_) g_cnt[threadIdx.x] = 0;
}

__global__ void router_kernel(const float* __restrict__ rtw, const float* __restrict__ rtb) {
    int lane = threadIdx.x & 31;
    int t = blockIdx.x*8 + (threadIdx.x >> 5);
    const float* xr = g_h + (size_t)t*D_;
    float acc[NE_];
#pragma unroll
    for (int e = 0; e < NE_; e++) acc[e] = 0.f;
    for (int d = lane; d < D_; d += 32) {
        float xv = xr[d];
#pragma unroll
        for (int e = 0; e < NE_; e++) acc[e] += xv * rtw[d*NE_ + e];
    }
#pragma unroll
    for (int off = 16; off > 0; off >>= 1)
#pragma unroll
        for (int e = 0; e < NE_; e++) acc[e] += __shfl_down_sync(0xffffffffu, acc[e], off);
    if (lane == 0) {
        float l0 = -1e30f, l1 = -1e30f; int e0 = 0, e1 = 0;
#pragma unroll
        for (int e = 0; e < NE_; e++) {
            float vv = acc[e] + rtb[e];
            if (vv > l0) { l1 = l0; e1 = e0; l0 = vv; e0 = e; }
            else if (vv > l1) { l1 = vv; e1 = e; }
        }
        float ew = expf(l1 - l0);          // normalized top-2 softmax weights
        float w0 = 1.f/(1.f + ew);
        float w1 = ew/(1.f + ew);
        int p0 = atomicAdd(&g_cnt[e0], 1); g_list[e0*T_ + p0] = t;
        int p1 = atomicAdd(&g_cnt[e1], 1); g_list[e1*T_ + p1] = t;
        g_ebuf[2*t]   = e0; g_pbuf[2*t]   = p0; g_wbuf[2*t]   = w0;
        g_ebuf[2*t+1] = e1; g_pbuf[2*t+1] = p1; g_wbuf[2*t+1] = w1;
    }
}

// ---------------- combine: h += w0*eo[e0,p0] + w1*eo[e1,p1] ----------------
__global__ void combine_kernel() {
    int t = blockIdx.x, d = threadIdx.x;
    float v = g_h[(size_t)t*D_ + d];
#pragma unroll
    for (int kk = 0; kk < 2; kk++) {
        int e = g_ebuf[2*t + kk];
        int p = g_pbuf[2*t + kk];
        float w = g_wbuf[2*t + kk];
        v += w * g_eo[((size_t)e*T_ + p)*D_ + d];
    }
    g_h[(size_t)t*D_ + d] = v;
}

// ---------------- head: LN(last token) -> pred / softplus(unc) ----------------
__global__ void head_kernel(const float* __restrict__ ln_g, const float* __restrict__ ln_b,
                            const float* __restrict__ pw, const float* __restrict__ pb,
                            const float* __restrict__ uw, const float* __restrict__ ub,
                            float* __restrict__ out) {
    __shared__ float red[256];
    __shared__ float norm[256];
    int b = blockIdx.x, d = threadIdx.x;
    float hv = g_h[(size_t)(b*L_ + L_ - 1)*D_ + d];
    red[d] = hv; __syncthreads();
    for (int s = 128; s > 0; s >>= 1) { if (d < s) red[d] += red[d+s]; __syncthreads(); }
    float mu = red[0] * (1.f/256.f);
    __syncthreads();
    float df = hv - mu;
    red[d] = df*df; __syncthreads();
    for (int s = 128; s > 0; s >>= 1) { if (d < s) red[d] += red[d+s]; __syncthreads(); }
    float var = red[0] * (1.f/256.f);
    norm[d] = df * rsqrtf(var + 1e-5f) * ln_g[d] + ln_b[d];
    __syncthreads();
    if (d < 2*NOUT_) {
        int o = d % NOUT_;
        bool un = (d >= NOUT_);
        const float* W = un ? uw : pw;
        float acc = un ? ub[o] : pb[o];
        for (int i = 0; i < D_; i++) acc += norm[i]*W[i*NOUT_ + o];
        if (!un) out[b*NOUT_ + o] = acc;
        else     out[B_*NOUT_ + b*NOUT_ + o] = (acc > 20.f) ? acc : log1pf(expf(acc));
    }
}

// ---------------- launch ----------------
extern "C" void kernel_launch(void* const* d_in, const int* in_sizes, int n_in,
                              void* d_out, int out_size) {
    const float* x     = (const float*)d_in[0];
    const float* emb_w = (const float*)d_in[1];
    const float* emb_b = (const float*)d_in[2];
    const float* wq    = (const float*)d_in[3];
    const float* wk    = (const float*)d_in[4];
    const float* wv    = (const float*)d_in[5];
    const float* wo    = (const float*)d_in[6];
    const float* wfreq = (const float*)d_in[7];
    const float* wph   = (const float*)d_in[8];
    const float* rtw   = (const float*)d_in[9];
    const float* rtb   = (const float*)d_in[10];
    const float* ew1   = (const float*)d_in[11];
    const float* eb1   = (const float*)d_in[12];
    const float* ew2   = (const float*)d_in[13];
    const float* eb2   = (const float*)d_in[14];
    const float* ln_g  = (const float*)d_in[15];
    const float* ln_b  = (const float*)d_in[16];
    const float* pw    = (const float*)d_in[17];
    const float* pb    = (const float*)d_in[18];
    const float* uw    = (const float*)d_in[19];
    const float* ub    = (const float*)d_in[20];
    float* out = (float*)d_out;

    float *ph, *pq, *pk, *pv, *pao, *peo, *phb;
    int *pcnt, *plist;
    cudaGetSymbolAddress((void**)&ph,   g_h);
    cudaGetSymbolAddress((void**)&pq,   g_q);
    cudaGetSymbolAddress((void**)&pk,   g_k);
    cudaGetSymbolAddress((void**)&pv,   g_v);
    cudaGetSymbolAddress((void**)&pao,  g_ao);
    cudaGetSymbolAddress((void**)&peo,  g_eo);
    cudaGetSymbolAddress((void**)&phb,  g_hb);
    cudaGetSymbolAddress((void**)&pcnt, g_cnt);
    cudaGetSymbolAddress((void**)&plist,g_list);

    cudaFuncSetAttribute(attn_mma, cudaFuncAttributeMaxDynamicSharedMemorySize, ATT_SMEM);
    cudaFuncSetAttribute(mma_gemm<EPI_NONE>,      cudaFuncAttributeMaxDynamicSharedMemorySize, GEMM_SMEM);
    cudaFuncSetAttribute(mma_gemm<EPI_RES>,       cudaFuncAttributeMaxDynamicSharedMemorySize, GEMM_SMEM);
    cudaFuncSetAttribute(mma_gemm<EPI_BIAS_GELU>, cudaFuncAttributeMaxDynamicSharedMemorySize, GEMM_SMEM);
    cudaFuncSetAttribute(mma_gemm<EPI_BIAS>,      cudaFuncAttributeMaxDynamicSharedMemorySize, GEMM_SMEM);

    embed_kernel<<<T_, D_>>>(x, emb_w, emb_b);

    for (int i = 0; i < NL_; i++) {
        const float* Wq = wq + (size_t)i*D_*D_;
        const float* Wk = wk + (size_t)i*D_*D_;
        const float* Wv = wv + (size_t)i*D_*D_;
        const float* Wo = wo + (size_t)i*D_*D_;

        // fused QKV: z selects (W, C)
        dim3 gqkv(T_/128, D_/128, 3);
        mma_gemm<EPI_NONE><<<gqkv, 256, GEMM_SMEM>>>(
            ph, D_, 0, Wq, Wk, Wv, D_, 0, pq, pk, pv, D_, 0,
            nullptr, 0, nullptr, nullptr, 0, nullptr, T_, D_, D_, 1);

        attn_mma<<<B_*H_, 256, ATT_SMEM>>>(pq, pk, pv, wfreq, wph, pao, i);

        dim3 gproj(T_/128, D_/128, 1);
        mma_gemm<EPI_RES><<<gproj, 256, GEMM_SMEM>>>(
            pao, D_, 0, Wo, nullptr, nullptr, D_, 0, ph, nullptr, nullptr, D_, 0,
            nullptr, 0, ph, nullptr, 0, nullptr, T_, D_, D_, 0);   // out proj + residual

        if (i % 2 == 0) {
            int m = i / 2;
            reset_kernel<<<1, 32>>>();
            router_kernel<<<T_/8, 256>>>(rtw + (size_t)m*D_*NE_, rtb + m*NE_);

            // FFN1: per expert, gathered rows of g_h: hb = gelu(x @ w1 + b1)
            dim3 g1(T_/128, DFF_/128, NE_);   // (128, 8, 8)
            mma_gemm<EPI_BIAS_GELU><<<g1, 256, GEMM_SMEM>>>(
                ph, D_, 0,
                ew1 + (size_t)m*NE_*D_*DFF_, nullptr, nullptr, DFF_, (size_t)D_*DFF_,
                phb, nullptr, nullptr, DFF_, (size_t)T_*DFF_,
                eb1 + (size_t)m*NE_*DFF_, DFF_,
                nullptr,
                plist, T_, pcnt,
                T_, DFF_, D_, 0);

            // FFN2: eo = hb @ w2 + b2
            dim3 g2(T_/128, D_/128, NE_);     // (128, 2, 8)
            mma_gemm<EPI_BIAS><<<g2, 256, GEMM_SMEM>>>(
                phb, DFF_, (size_t)T_*DFF_,
                ew2 + (size_t)m*NE_*DFF_*D_, nullptr, nullptr, D_, (size_t)DFF_*D_,
                peo, nullptr, nullptr, D_, (size_t)T_*D_,
                eb2 + (size_t)m*NE_*D_, D_,
                nullptr,
                nullptr, 0, pcnt,
                T_, D_, DFF_, 0);

            combine_kernel<<<T_, D_>>>();
        }
    }
    head_kernel<<<B_, D_>>>(ln_g, ln_b, pw, pb, uw, ub, out);
}

// round 8
// speedup vs baseline: 1.9856x; 1.0670x over previous
#include <cuda_runtime.h>
#include <math.h>
#include <stdint.h>

#define B_ 128
#define L_ 128
#define T_ (B_*L_)
#define DIN_ 6
#define D_ 256
#define H_ 8
#define DK_ 32
#define NL_ 6
#define NE_ 8
#define DFF_ 1024
#define NOUT_ 5

// ---------------- device scratch (no allocations allowed) ----------------
__device__ float g_h[T_*D_];
__device__ float g_q[T_*D_];
__device__ float g_k[T_*D_];
__device__ float g_v[T_*D_];
__device__ float g_ao[T_*D_];
__device__ float g_eo[(size_t)NE_*T_*D_];     // per-expert FFN outputs by list position
__device__ float g_hb[(size_t)NE_*T_*DFF_];   // FFN hidden (gelu output), per (e, pos)
__device__ int   g_cnt[NE_];
__device__ int   g_list[NE_*T_];
__device__ int   g_ebuf[T_*2];
__device__ int   g_pbuf[T_*2];
__device__ float g_wbuf[T_*2];

__device__ __forceinline__ uint32_t f2tf(float x) {
    uint32_t u;
    asm("cvt.rna.tf32.f32 %0, %1;" : "=r"(u) : "f"(x));
    return u;
}

// ---------------- embed: h = x @ emb_w + emb_b ----------------
__global__ void embed_kernel(const float* __restrict__ x,
                             const float* __restrict__ w,
                             const float* __restrict__ b) {
    int t = blockIdx.x, d = threadIdx.x;
    float acc = b[d];
#pragma unroll
    for (int i = 0; i < DIN_; i++) acc += x[t*DIN_ + i] * w[i*D_ + d];
    g_h[(size_t)t*D_ + d] = acc;
}

// ---------------- TF32 tensor-core GEMM, 3-stage cp.async pipeline ----------------
// C[M,N] = A[M,K] @ W[K,N]  (both row-major), fused epilogues.
// Block tile 128x128, 8 warps (4M x 2N), warp tile 32x64, K-chunk 32.
// A tile XOR-swizzled (no padding), B tile padded to 136.
#define EPI_NONE      0
#define EPI_RES       1
#define EPI_BIAS_GELU 2
#define EPI_BIAS      3

#define LDB_S 136
#define A_ST (128*32)       // 4096 floats, swizzled
#define B_ST (32*LDB_S)     // 4352 floats
#define GEMM_SMEM ((3*A_ST + 3*B_ST)*4)   // 101376 bytes

template<int EPI>
__global__ __launch_bounds__(256, 2)
void mma_gemm(const float* __restrict__ A, int lda, size_t strideA,
              const float* __restrict__ W, const float* __restrict__ W2,
              const float* __restrict__ W3, int ldw, size_t strideW,
              float* __restrict__ C, float* __restrict__ C2, float* __restrict__ C3,
              int ldc, size_t strideC,
              const float* __restrict__ bias, size_t strideBias,
              const float* __restrict__ res,
              const int* __restrict__ gather, size_t strideGather,
              const int* __restrict__ cntPtr,
              int M, int N, int K, int qkv) {
    extern __shared__ float sm[];

    int e = blockIdx.z;
    const float* Ae = A;
    const float* We;
    float*       Ce;
    const float* be = nullptr;
    const int*   ge = nullptr;
    int Mloc = M;
    if (qkv) {
        We = (e == 0) ? W : (e == 1) ? W2 : W3;
        Ce = (e == 0) ? C : (e == 1) ? C2 : C3;
    } else {
        Ae = A + (size_t)e*strideA;
        We = W + (size_t)e*strideW;
        Ce = C + (size_t)e*strideC;
        if (bias)   be = bias + (size_t)e*strideBias;
        if (gather) ge = gather + (size_t)e*strideGather;
        if (cntPtr) Mloc = cntPtr[e];
    }

    int bm = blockIdx.x * 128;
    if (bm >= Mloc) return;
    int bn = blockIdx.y * 128;

    int tid = threadIdx.x;
    int lane = tid & 31;
    int wid = tid >> 5;
    int wm = wid & 3;        // 0..3  M direction
    int wn = wid >> 2;       // 0..1  N direction

    // ---- per-thread load descriptors (k0-independent) ----
    const float* asrc[4]; int apred[4]; int aoff[4];
    const float* bsrc[4]; int boff[4];
#pragma unroll
    for (int p = 0; p < 4; p++) {
        int f = tid + p*256;
        int r = f >> 3, g = f & 7;           // row, 4-float group
        int grow = bm + r;
        apred[p] = (grow < Mloc) ? 16 : 0;
        int gc = (grow < Mloc) ? grow : 0;
        int arow = ge ? ge[gc] : gc;
        asrc[p] = Ae + (size_t)arow*lda + (g << 2);
        aoff[p] = r*32 + ((g ^ (r & 7)) << 2);   // XOR swizzle
        int kr = f >> 5, d4 = (f & 31) << 2;
        bsrc[p] = We + (size_t)kr*ldw + bn + d4;
        boff[p] = kr*LDB_S + d4;
    }
    uint32_t sA[3], sB[3];
#pragma unroll
    for (int s = 0; s < 3; s++) {
        sA[s] = (uint32_t)__cvta_generic_to_shared(sm + s*A_ST);
        sB[s] = (uint32_t)__cvta_generic_to_shared(sm + 3*A_ST + s*B_ST);
    }

    auto load_stage = [&](int st, int ki) {
        int k0 = ki << 5;
#pragma unroll
        for (int p = 0; p < 4; p++) {
            uint32_t da = sA[st] + (uint32_t)(aoff[p]*4);
            asm volatile("cp.async.ca.shared.global [%0], [%1], 16, %2;"
                         :: "r"(da), "l"(asrc[p] + k0), "r"(apred[p]));
        }
#pragma unroll
        for (int p = 0; p < 4; p++) {
            uint32_t db = sB[st] + (uint32_t)(boff[p]*4);
            asm volatile("cp.async.ca.shared.global [%0], [%1], 16;"
                         :: "r"(db), "l"(bsrc[p] + (size_t)k0*ldw));
        }
        asm volatile("cp.async.commit_group;");
    };

    float acc[2][8][4];
#pragma unroll
    for (int mt = 0; mt < 2; mt++)
#pragma unroll
        for (int nt = 0; nt < 8; nt++)
#pragma unroll
            for (int i = 0; i < 4; i++) acc[mt][nt][i] = 0.f;

    int nk = K >> 5;
    load_stage(0, 0);
    load_stage(1, 1);

    int sw = lane >> 2;                        // A swizzle key for fragment reads
    int st = 0;
    for (int ki = 0; ki < nk; ki++) {
        if (ki == nk - 1) asm volatile("cp.async.wait_group 0;");
        else              asm volatile("cp.async.wait_group 1;");
        __syncthreads();
        if (ki + 2 < nk) {
            int st2 = st + 2; if (st2 >= 3) st2 -= 3;
            load_stage(st2, ki + 2);
        }

        const float* As = sm + st*A_ST;
        const float* Bs = sm + 3*A_ST + st*B_ST;
        const float* ar0 = As + (wm*32 + (lane >> 2))*32 + (lane & 3);
        const float* br0 = Bs + (lane & 3)*LDB_S + wn*64 + (lane >> 2);
#pragma unroll
        for (int kk = 0; kk < 32; kk += 8) {
            int g0 = kk >> 2;
            int off0 = ((g0 ^ sw) << 2);
            int off1 = (((g0 + 1) ^ sw) << 2);
            uint32_t af[2][4];
#pragma unroll
            for (int mt = 0; mt < 2; mt++) {
                const float* ar = ar0 + mt*512;
                af[mt][0] = __float_as_uint(ar[off0]);
                af[mt][1] = __float_as_uint(ar[256 + off0]);
                af[mt][2] = __float_as_uint(ar[off1]);
                af[mt][3] = __float_as_uint(ar[256 + off1]);
            }
            uint32_t bf[8][2];
#pragma unroll
            for (int nt = 0; nt < 8; nt++) {
                const float* br = br0 + kk*LDB_S + nt*8;
                bf[nt][0] = __float_as_uint(br[0]);
                bf[nt][1] = __float_as_uint(br[4*LDB_S]);
            }
#pragma unroll
            for (int mt = 0; mt < 2; mt++)
#pragma unroll
                for (int nt = 0; nt < 8; nt++) {
                    asm volatile(
                        "mma.sync.aligned.m16n8k8.row.col.f32.tf32.tf32.f32 "
                        "{%0,%1,%2,%3}, {%4,%5,%6,%7}, {%8,%9}, {%0,%1,%2,%3};"
                        : "+f"(acc[mt][nt][0]), "+f"(acc[mt][nt][1]),
                          "+f"(acc[mt][nt][2]), "+f"(acc[mt][nt][3])
                        : "r"(af[mt][0]), "r"(af[mt][1]), "r"(af[mt][2]), "r"(af[mt][3]),
                          "r"(bf[nt][0]), "r"(bf[nt][1]));
                }
        }
        __syncthreads();
        if (++st == 3) st = 0;
    }

    // ---- epilogue (float2 pairs) ----
#pragma unroll
    for (int mt = 0; mt < 2; mt++) {
#pragma unroll
        for (int nt = 0; nt < 8; nt++) {
            int row0 = bm + wm*32 + mt*16 + (lane >> 2);
            int col  = bn + wn*64 + nt*8 + ((lane & 3) << 1);
#pragma unroll
            for (int h = 0; h < 2; h++) {
                int row = row0 + 8*h;
                if (row < Mloc) {
                    float v0 = acc[mt][nt][2*h];
                    float v1 = acc[mt][nt][2*h + 1];
                    if (EPI == EPI_BIAS_GELU) {
                        v0 += be[col];     v1 += be[col + 1];
                        v0 = 0.5f*v0*(1.f + erff(v0*0.7071067811865475f));
                        v1 = 0.5f*v1*(1.f + erff(v1*0.7071067811865475f));
                    } else if (EPI == EPI_BIAS) {
                        v0 += be[col];     v1 += be[col + 1];
                    } else if (EPI == EPI_RES) {
                        float2 r2 = *(const float2*)(res + (size_t)row*ldc + col);
                        v0 += r2.x;        v1 += r2.y;
                    }
                    float2 o2; o2.x = v0; o2.y = v1;
                    *(float2*)(Ce + (size_t)row*ldc + col) = o2;
                }
            }
        }
    }
}

// ---------------- tensor-core wave attention: one block per (b, head) ----------------
#define LDPS 132
#define LDQ  36
#define LDK  136
#define LDV  36
#define OFF_KS  (128*LDQ)                 // 4608
#define OFF_VS  (128*LDPS)                // 16896
#define OFF_WAV (OFF_VS + 128*LDV)        // 21504
#define OFF_RED (OFF_WAV + 128)           // 21632
#define ATT_SMEM ((OFF_RED + 256)*4)      // 87552 bytes

__global__ __launch_bounds__(256)
void attn_mma(const float* __restrict__ q, const float* __restrict__ k,
              const float* __restrict__ v, const float* __restrict__ wfreq,
              const float* __restrict__ wphase, float* __restrict__ out, int layer) {
    extern __shared__ float sm[];
    float* Ps  = sm;             // [128][132]  (phase 2; aliases Qs/Ks)
    float* Qs  = sm;             // [128][36]   (phase 1)
    float* Ks  = sm + OFF_KS;    // [32][136]   (phase 1)
    float* Vs  = sm + OFF_VS;    // [128][36]
    float* wav = sm + OFF_WAV;   // [128] wave*scale, later inv row sums
    float* red = sm + OFF_RED;   // [128][2] cross-warp reductions

    int b = blockIdx.x >> 3, hh = blockIdx.x & 7;
    int tid = threadIdx.x, lane = tid & 31, wid = tid >> 5;
    int wm = wid & 3, wn = wid >> 2;

    const float* qb = q + (size_t)(b*L_)*D_ + hh*DK_;
    const float* kb = k + (size_t)(b*L_)*D_ + hh*DK_;
    const float* vb = v + (size_t)(b*L_)*D_ + hh*DK_;

    if (tid < L_) {
        float fr = wfreq[layer*H_ + hh], ph = wphase[layer*H_ + hh];
        wav[tid] = cosf(6.283185307179586f*fr*(float)tid + ph) * 0.17677669529663688f;
    }

    // ---- load Q[m][d], K^T[d][j], V[j][d] tiles (tf32) ----
#pragma unroll
    for (int p = 0; p < 4; p++) {
        int f = tid + p*256;
        int r = f >> 3;              // 0..127 (m for Q, j for K/V)
        int c4 = (f & 7) << 2;       // d base
        float4 vq = *(const float4*)(qb + (size_t)r*D_ + c4);
        Qs[r*LDQ + c4 + 0] = __uint_as_float(f2tf(vq.x));
        Qs[r*LDQ + c4 + 1] = __uint_as_float(f2tf(vq.y));
        Qs[r*LDQ + c4 + 2] = __uint_as_float(f2tf(vq.z));
        Qs[r*LDQ + c4 + 3] = __uint_as_float(f2tf(vq.w));
        float4 vk = *(const float4*)(kb + (size_t)r*D_ + c4);
        Ks[(c4 + 0)*LDK + r] = __uint_as_float(f2tf(vk.x));
        Ks[(c4 + 1)*LDK + r] = __uint_as_float(f2tf(vk.y));
        Ks[(c4 + 2)*LDK + r] = __uint_as_float(f2tf(vk.z));
        Ks[(c4 + 3)*LDK + r] = __uint_as_float(f2tf(vk.w));
        float4 vv = *(const float4*)(vb + (size_t)r*D_ + c4);
        Vs[r*LDV + c4 + 0] = __uint_as_float(f2tf(vv.x));
        Vs[r*LDV + c4 + 1] = __uint_as_float(f2tf(vv.y));
        Vs[r*LDV + c4 + 2] = __uint_as_float(f2tf(vv.z));
        Vs[r*LDV + c4 + 3] = __uint_as_float(f2tf(vv.w));
    }
    __syncthreads();

    // ---- mma1: scores 128x128, K-dim = 32 ----
    float acc[2][8][4];
#pragma unroll
    for (int mt = 0; mt < 2; mt++)
#pragma unroll
        for (int nt = 0; nt < 8; nt++)
#pragma unroll
            for (int i = 0; i < 4; i++) acc[mt][nt][i] = 0.f;
    {
        const float* ar0 = Qs + (wm*32 + (lane >> 2))*LDQ + (lane & 3);
        const float* br0 = Ks + (lane & 3)*LDK + wn*64 + (lane >> 2);
#pragma unroll
        for (int kk = 0; kk < 32; kk += 8) {
            uint32_t af[2][4];
#pragma unroll
            for (int mt = 0; mt < 2; mt++) {
                const float* ar = ar0 + mt*16*LDQ + kk;
                af[mt][0] = __float_as_uint(ar[0]);
                af[mt][1] = __float_as_uint(ar[8*LDQ]);
                af[mt][2] = __float_as_uint(ar[4]);
                af[mt][3] = __float_as_uint(ar[8*LDQ + 4]);
            }
            uint32_t bf[8][2];
#pragma unroll
            for (int nt = 0; nt < 8; nt++) {
                const float* br = br0 + kk*LDK + nt*8;
                bf[nt][0] = __float_as_uint(br[0]);
                bf[nt][1] = __float_as_uint(br[4*LDK]);
            }
#pragma unroll
            for (int mt = 0; mt < 2; mt++)
#pragma unroll
                for (int nt = 0; nt < 8; nt++) {
                    asm volatile(
                        "mma.sync.aligned.m16n8k8.row.col.f32.tf32.tf32.f32 "
                        "{%0,%1,%2,%3}, {%4,%5,%6,%7}, {%8,%9}, {%0,%1,%2,%3};"
                        : "+f"(acc[mt][nt][0]), "+f"(acc[mt][nt][1]),
                          "+f"(acc[mt][nt][2]), "+f"(acc[mt][nt][3])
                        : "r"(af[mt][0]), "r"(af[mt][1]), "r"(af[mt][2]), "r"(af[mt][3]),
                          "r"(bf[nt][0]), "r"(bf[nt][1]));
                }
        }
    }
    __syncthreads();   // Qs/Ks dead; Ps region reusable after softmax writes

    // ---- wave * scale, row max ----
    float rmax[2][2] = {{-1e30f, -1e30f}, {-1e30f, -1e30f}};
#pragma unroll
    for (int mt = 0; mt < 2; mt++)
#pragma unroll
        for (int nt = 0; nt < 8; nt++)
#pragma unroll
            for (int i = 0; i < 4; i++) {
                int col = wn*64 + nt*8 + ((lane & 3) << 1) + (i & 1);
                float s = acc[mt][nt][i] * wav[col];
                acc[mt][nt][i] = s;
                rmax[mt][i >> 1] = fmaxf(rmax[mt][i >> 1], s);
            }
#pragma unroll
    for (int mt = 0; mt < 2; mt++)
#pragma unroll
        for (int h2 = 0; h2 < 2; h2++) {
            float m = rmax[mt][h2];
            m = fmaxf(m, __shfl_xor_sync(0xffffffffu, m, 1));
            m = fmaxf(m, __shfl_xor_sync(0xffffffffu, m, 2));
            rmax[mt][h2] = m;
        }
    if ((lane & 3) == 0) {
#pragma unroll
        for (int mt = 0; mt < 2; mt++)
#pragma unroll
            for (int h2 = 0; h2 < 2; h2++) {
                int row = wm*32 + mt*16 + (lane >> 2) + 8*h2;
                red[row*2 + wn] = rmax[mt][h2];
            }
    }
    __syncthreads();
    float rm[2][2];
#pragma unroll
    for (int mt = 0; mt < 2; mt++)
#pragma unroll
        for (int h2 = 0; h2 < 2; h2++) {
            int row = wm*32 + mt*16 + (lane >> 2) + 8*h2;
            rm[mt][h2] = fmaxf(red[row*2], red[row*2 + 1]);
        }

    // ---- exp, row sum ----
    float rsum[2][2] = {{0.f, 0.f}, {0.f, 0.f}};
#pragma unroll
    for (int mt = 0; mt < 2; mt++)
#pragma unroll
        for (int nt = 0; nt < 8; nt++)
#pragma unroll
            for (int i = 0; i < 4; i++) {
                float e = __expf(acc[mt][nt][i] - rm[mt][i >> 1]);
                acc[mt][nt][i] = e;
                rsum[mt][i >> 1] += e;
            }
#pragma unroll
    for (int mt = 0; mt < 2; mt++)
#pragma unroll
        for (int h2 = 0; h2 < 2; h2++) {
            float s = rsum[mt][h2];
            s += __shfl_xor_sync(0xffffffffu, s, 1);
            s += __shfl_xor_sync(0xffffffffu, s, 2);
            rsum[mt][h2] = s;
        }
    __syncthreads();   // max reads done; red reusable for sums
    if ((lane & 3) == 0) {
#pragma unroll
        for (int mt = 0; mt < 2; mt++)
#pragma unroll
            for (int h2 = 0; h2 < 2; h2++) {
                int row = wm*32 + mt*16 + (lane >> 2) + 8*h2;
                red[row*2 + wn] = rsum[mt][h2];
            }
    }
    __syncthreads();
    // inverse row sums -> wav (wav dead), and P -> Ps (tf32)
    if (wn == 0 && (lane & 3) == 0) {
#pragma unroll
        for (int mt = 0; mt < 2; mt++)
#pragma unroll
            for (int h2 = 0; h2 < 2; h2++) {
                int row = wm*32 + mt*16 + (lane >> 2) + 8*h2;
                wav[row] = 1.f / (red[row*2] + red[row*2 + 1]);
            }
    }
#pragma unroll
    for (int mt = 0; mt < 2; mt++)
#pragma unroll
        for (int nt = 0; nt < 8; nt++)
#pragma unroll
            for (int i = 0; i < 4; i++) {
                int row = wm*32 + mt*16 + (lane >> 2) + 8*(i >> 1);
                int col = wn*64 + nt*8 + ((lane & 3) << 1) + (i & 1);
                Ps[row*LDPS + col] = __uint_as_float(f2tf(acc[mt][nt][i]));
            }
    __syncthreads();

    // ---- mma2: O = P @ V, 8 warps over M (16 rows each), N=32, K=128 ----
    float o[4][4];
#pragma unroll
    for (int nt = 0; nt < 4; nt++)
#pragma unroll
        for (int i = 0; i < 4; i++) o[nt][i] = 0.f;
    {
        const float* ar2 = Ps + (wid*16 + (lane >> 2))*LDPS + (lane & 3);
        const float* br2 = Vs + (lane & 3)*LDV + (lane >> 2);
#pragma unroll
        for (int kk = 0; kk < 128; kk += 8) {
            uint32_t af[4];
            af[0] = __float_as_uint(ar2[kk]);
            af[1] = __float_as_uint(ar2[8*LDPS + kk]);
            af[2] = __float_as_uint(ar2[kk + 4]);
            af[3] = __float_as_uint(ar2[8*LDPS + kk + 4]);
#pragma unroll
            for (int nt = 0; nt < 4; nt++) {
                uint32_t b0 = __float_as_uint(br2[kk*LDV + nt*8]);
                uint32_t b1 = __float_as_uint(br2[(kk + 4)*LDV + nt*8]);
                asm volatile(
                    "mma.sync.aligned.m16n8k8.row.col.f32.tf32.tf32.f32 "
                    "{%0,%1,%2,%3}, {%4,%5,%6,%7}, {%8,%9}, {%0,%1,%2,%3};"
                    : "+f"(o[nt][0]), "+f"(o[nt][1]), "+f"(o[nt][2]), "+f"(o[nt][3])
                    : "r"(af[0]), "r"(af[1]), "r"(af[2]), "r"(af[3]),
                      "r"(b0), "r"(b1));
            }
        }
    }

    // ---- epilogue: normalize by row sum, store ----
    float is0 = wav[wid*16 + (lane >> 2)];
    float is1 = wav[wid*16 + (lane >> 2) + 8];
#pragma unroll
    for (int nt = 0; nt < 4; nt++)
#pragma unroll
        for (int i = 0; i < 4; i++) {
            int row = wid*16 + (lane >> 2) + 8*(i >> 1);
            int col = nt*8 + ((lane & 3) << 1) + (i & 1);
            out[(size_t)(b*L_ + row)*D_ + hh*DK_ + col] = o[nt][i] * ((i >> 1) ? is1 : is0);
        }
}

// ---------------- MoE router + bucketing (one warp per token) ----------------
__global__ void reset_kernel() {
    if (threadIdx.x < NE_) g_cnt[threadIdx.x] = 0;
}

__global__ void router_kernel(const float* __restrict__ rtw, const float* __restrict__ rtb) {
    int lane = threadIdx.x & 31;
    int t = blockIdx.x*8 + (threadIdx.x >> 5);
    const float* xr = g_h + (size_t)t*D_;
    float acc[NE_];
#pragma unroll
    for (int e = 0; e < NE_; e++) acc[e] = 0.f;
    for (int d = lane; d < D_; d += 32) {
        float xv = xr[d];
#pragma unroll
        for (int e = 0; e < NE_; e++) acc[e] += xv * rtw[d*NE_ + e];
    }
#pragma unroll
    for (int off = 16; off > 0; off >>= 1)
#pragma unroll
        for (int e = 0; e < NE_; e++) acc[e] += __shfl_down_sync(0xffffffffu, acc[e], off);
    if (lane == 0) {
        float l0 = -1e30f, l1 = -1e30f; int e0 = 0, e1 = 0;
#pragma unroll
        for (int e = 0; e < NE_; e++) {
            float vv = acc[e] + rtb[e];
            if (vv > l0) { l1 = l0; e1 = e0; l0 = vv; e0 = e; }
            else if (vv > l1) { l1 = vv; e1 = e; }
        }
        float ew = expf(l1 - l0);          // normalized top-2 softmax weights
        float w0 = 1.f/(1.f + ew);
        float w1 = ew/(1.f + ew);
        int p0 = atomicAdd(&g_cnt[e0], 1); g_list[e0*T_ + p0] = t;
        int p1 = atomicAdd(&g_cnt[e1], 1); g_list[e1*T_ + p1] = t;
        g_ebuf[2*t]   = e0; g_pbuf[2*t]   = p0; g_wbuf[2*t]   = w0;
        g_ebuf[2*t+1] = e1; g_pbuf[2*t+1] = p1; g_wbuf[2*t+1] = w1;
    }
}

// ---------------- combine: h += w0*eo[e0,p0] + w1*eo[e1,p1] ----------------
__global__ void combine_kernel() {
    int t = blockIdx.x, d = threadIdx.x;
    float v = g_h[(size_t)t*D_ + d];
#pragma unroll
    for (int kk = 0; kk < 2; kk++) {
        int e = g_ebuf[2*t + kk];
        int p = g_pbuf[2*t + kk];
        float w = g_wbuf[2*t + kk];
        v += w * g_eo[((size_t)e*T_ + p)*D_ + d];
    }
    g_h[(size_t)t*D_ + d] = v;
}

// ---------------- head: LN(last token) -> pred / softplus(unc) ----------------
__global__ void head_kernel(const float* __restrict__ ln_g, const float* __restrict__ ln_b,
                            const float* __restrict__ pw, const float* __restrict__ pb,
                            const float* __restrict__ uw, const float* __restrict__ ub,
                            float* __restrict__ out) {
    __shared__ float red[256];
    __shared__ float norm[256];
    int b = blockIdx.x, d = threadIdx.x;
    float hv = g_h[(size_t)(b*L_ + L_ - 1)*D_ + d];
    red[d] = hv; __syncthreads();
    for (int s = 128; s > 0; s >>= 1) { if (d < s) red[d] += red[d+s]; __syncthreads(); }
    float mu = red[0] * (1.f/256.f);
    __syncthreads();
    float df = hv - mu;
    red[d] = df*df; __syncthreads();
    for (int s = 128; s > 0; s >>= 1) { if (d < s) red[d] += red[d+s]; __syncthreads(); }
    float var = red[0] * (1.f/256.f);
    norm[d] = df * rsqrtf(var + 1e-5f) * ln_g[d] + ln_b[d];
    __syncthreads();
    if (d < 2*NOUT_) {
        int o = d % NOUT_;
        bool un = (d >= NOUT_);
        const float* W = un ? uw : pw;
        float acc = un ? ub[o] : pb[o];
        for (int i = 0; i < D_; i++) acc += norm[i]*W[i*NOUT_ + o];
        if (!un) out[b*NOUT_ + o] = acc;
        else     out[B_*NOUT_ + b*NOUT_ + o] = (acc > 20.f) ? acc : log1pf(expf(acc));
    }
}

// ---------------- launch ----------------
extern "C" void kernel_launch(void* const* d_in, const int* in_sizes, int n_in,
                              void* d_out, int out_size) {
    const float* x     = (const float*)d_in[0];
    const float* emb_w = (const float*)d_in[1];
    const float* emb_b = (const float*)d_in[2];
    const float* wq    = (const float*)d_in[3];
    const float* wk    = (const float*)d_in[4];
    const float* wv    = (const float*)d_in[5];
    const float* wo    = (const float*)d_in[6];
    const float* wfreq = (const float*)d_in[7];
    const float* wph   = (const float*)d_in[8];
    const float* rtw   = (const float*)d_in[9];
    const float* rtb   = (const float*)d_in[10];
    const float* ew1   = (const float*)d_in[11];
    const float* eb1   = (const float*)d_in[12];
    const float* ew2   = (const float*)d_in[13];
    const float* eb2   = (const float*)d_in[14];
    const float* ln_g  = (const float*)d_in[15];
    const float* ln_b  = (const float*)d_in[16];
    const float* pw    = (const float*)d_in[17];
    const float* pb    = (const float*)d_in[18];
    const float* uw    = (const float*)d_in[19];
    const float* ub    = (const float*)d_in[20];
    float* out = (float*)d_out;

    float *ph, *pq, *pk, *pv, *pao, *peo, *phb;
    int *pcnt, *plist;
    cudaGetSymbolAddress((void**)&ph,   g_h);
    cudaGetSymbolAddress((void**)&pq,   g_q);
    cudaGetSymbolAddress((void**)&pk,   g_k);
    cudaGetSymbolAddress((void**)&pv,   g_v);
    cudaGetSymbolAddress((void**)&pao,  g_ao);
    cudaGetSymbolAddress((void**)&peo,  g_eo);
    cudaGetSymbolAddress((void**)&phb,  g_hb);
    cudaGetSymbolAddress((void**)&pcnt, g_cnt);
    cudaGetSymbolAddress((void**)&plist,g_list);

    cudaFuncSetAttribute(attn_mma, cudaFuncAttributeMaxDynamicSharedMemorySize, ATT_SMEM);
    cudaFuncSetAttribute(mma_gemm<EPI_NONE>,      cudaFuncAttributeMaxDynamicSharedMemorySize, GEMM_SMEM);
    cudaFuncSetAttribute(mma_gemm<EPI_RES>,       cudaFuncAttributeMaxDynamicSharedMemorySize, GEMM_SMEM);
    cudaFuncSetAttribute(mma_gemm<EPI_BIAS_GELU>, cudaFuncAttributeMaxDynamicSharedMemorySize, GEMM_SMEM);
    cudaFuncSetAttribute(mma_gemm<EPI_BIAS>,      cudaFuncAttributeMaxDynamicSharedMemorySize, GEMM_SMEM);

    embed_kernel<<<T_, D_>>>(x, emb_w, emb_b);

    for (int i = 0; i < NL_; i++) {
        const float* Wq = wq + (size_t)i*D_*D_;
        const float* Wk = wk + (size_t)i*D_*D_;
        const float* Wv = wv + (size_t)i*D_*D_;
        const float* Wo = wo + (size_t)i*D_*D_;

        // fused QKV: z selects (W, C)
        dim3 gqkv(T_/128, D_/128, 3);
        mma_gemm<EPI_NONE><<<gqkv, 256, GEMM_SMEM>>>(
            ph, D_, 0, Wq, Wk, Wv, D_, 0, pq, pk, pv, D_, 0,
            nullptr, 0, nullptr, nullptr, 0, nullptr, T_, D_, D_, 1);

        attn_mma<<<B_*H_, 256, ATT_SMEM>>>(pq, pk, pv, wfreq, wph, pao, i);

        dim3 gproj(T_/128, D_/128, 1);
        mma_gemm<EPI_RES><<<gproj, 256, GEMM_SMEM>>>(
            pao, D_, 0, Wo, nullptr, nullptr, D_, 0, ph, nullptr, nullptr, D_, 0,
            nullptr, 0, ph, nullptr, 0, nullptr, T_, D_, D_, 0);   // out proj + residual

        if (i % 2 == 0) {
            int m = i / 2;
            reset_kernel<<<1, 32>>>();
            router_kernel<<<T_/8, 256>>>(rtw + (size_t)m*D_*NE_, rtb + m*NE_);

            // FFN1: per expert, gathered rows of g_h: hb = gelu(x @ w1 + b1)
            dim3 g1(T_/128, DFF_/128, NE_);   // (128, 8, 8)
            mma_gemm<EPI_BIAS_GELU><<<g1, 256, GEMM_SMEM>>>(
                ph, D_, 0,
                ew1 + (size_t)m*NE_*D_*DFF_, nullptr, nullptr, DFF_, (size_t)D_*DFF_,
                phb, nullptr, nullptr, DFF_, (size_t)T_*DFF_,
                eb1 + (size_t)m*NE_*DFF_, DFF_,
                nullptr,
                plist, T_, pcnt,
                T_, DFF_, D_, 0);

            // FFN2: eo = hb @ w2 + b2
            dim3 g2(T_/128, D_/128, NE_);     // (128, 2, 8)
            mma_gemm<EPI_BIAS><<<g2, 256, GEMM_SMEM>>>(
                phb, DFF_, (size_t)T_*DFF_,
                ew2 + (size_t)m*NE_*DFF_*D_, nullptr, nullptr, D_, (size_t)DFF_*D_,
                peo, nullptr, nullptr, D_, (size_t)T_*D_,
                eb2 + (size_t)m*NE_*D_, D_,
                nullptr,
                nullptr, 0, pcnt,
                T_, D_, DFF_, 0);

            combine_kernel<<<T_, D_>>>();
        }
    }
    head_kernel<<<B_, D_>>>(ln_g, ln_b, pw, pb, uw, ub, out);
}